// round 10
// baseline (speedup 1.0000x reference)
#include <cuda_runtime.h>
#include <cstdint>

#define NNODES 100000
#define NEDGES 1600000
#define FDIM   128
#define NC     4          // pipeline chunks

// Scratch (device globals — no allocation allowed anywhere)
__device__ float g_h [(size_t)NNODES * FDIM];  // layer-1 messages (dis-scaled)
__device__ float g_h2[(size_t)NNODES * FDIM];  // layer-2 messages (dis-scaled)
__device__ float g_a [(size_t)NNODES * FDIM];  // aggregated features
__device__ float g_g3[(size_t)NNODES * 40];    // layer-3 fused messages
__device__ float g_dis[NNODES];                // (deg+1)^{-1/2}
__device__ int   g_deg[NNODES];
__device__ int   g_rowp[NNODES + 1];
__device__ int   g_cursor[NNODES];
__device__ int   g_col[NEDGES];
__device__ int   g_bsum[512];
__device__ int   g_boff[512];
__device__ int   g_is64;
__device__ float g_Wc[128 * 40];               // W3 @ Wl
__device__ float g_bc[40];                     // b3 @ Wl + bl

// ===========================================================================
// Edge dtype detection
// ===========================================================================
__global__ void k_init_flag() { g_is64 = 1; }

__global__ void k_detect(const int* __restrict__ p, int twoE) {
    int i = blockIdx.x * blockDim.x + threadIdx.x;
    int idx = 2 * i + 1;
    if (idx < twoE && p[idx] != 0) g_is64 = 0;
}

__device__ __forceinline__ int load_edge(const void* ei, size_t idx, int is64) {
    if (is64) return (int)((const long long*)ei)[idx];
    return ((const int*)ei)[idx];
}

// ===========================================================================
// Weight fusion: Wc = W3 @ Wl, bc = b3 @ Wl + bl
// ===========================================================================
__global__ void __launch_bounds__(256) k_fuseW(const float* __restrict__ W3,
                                               const float* __restrict__ Wl,
                                               const float* __restrict__ b3,
                                               const float* __restrict__ bl)
{
    __shared__ float Wls[128 * 40];
    int tid = threadIdx.x;
    for (int i = tid; i < 128 * 40; i += 256) Wls[i] = Wl[i];
    __syncthreads();

    for (int o = tid; o < 128 * 40; o += 256) {
        int i = o / 40, n = o % 40;
        float s = 0.f;
        #pragma unroll 8
        for (int k = 0; k < 128; k++)
            s = fmaf(W3[(size_t)i * FDIM + k], Wls[k * 40 + n], s);
        g_Wc[o] = s;
    }
    if (tid < 40) {
        float s = bl[tid];
        #pragma unroll 8
        for (int k = 0; k < 128; k++)
            s = fmaf(b3[k], Wls[k * 40 + tid], s);
        g_bc[tid] = s;
    }
}

// ===========================================================================
// CSR build
// ===========================================================================
__global__ void k_zero_deg(int n) {
    int i = blockIdx.x * blockDim.x + threadIdx.x;
    if (i < n) g_deg[i] = 0;
}

__global__ void k_count_deg(const void* __restrict__ ei, int E, int n) {
    int e = blockIdx.x * blockDim.x + threadIdx.x;
    if (e >= E) return;
    int is64 = g_is64;
    int d = load_edge(ei, (size_t)E + e, is64);
    if ((unsigned)d < (unsigned)n) atomicAdd(&g_deg[d], 1);
}

__global__ void k_dis(int n) {
    int i = blockIdx.x * blockDim.x + threadIdx.x;
    if (i < n) g_dis[i] = rsqrtf((float)(g_deg[i] + 1));
}

__global__ void __launch_bounds__(256) k_scan_block(int n) {
    __shared__ int s[256];
    int tid = threadIdx.x;
    int i = blockIdx.x * 256 + tid;
    int v = (i < n) ? g_deg[i] : 0;
    s[tid] = v;
    __syncthreads();
    for (int off = 1; off < 256; off <<= 1) {
        int t = (tid >= off) ? s[tid - off] : 0;
        __syncthreads();
        s[tid] += t;
        __syncthreads();
    }
    if (i < n) g_rowp[i] = s[tid] - v;
    if (tid == 255 && blockIdx.x < 512) g_bsum[blockIdx.x] = s[255];
}

__global__ void __launch_bounds__(512) k_scan_spine(int nb) {
    __shared__ int s[512];
    int tid = threadIdx.x;
    int v = (tid < nb) ? g_bsum[tid] : 0;
    s[tid] = v;
    __syncthreads();
    for (int off = 1; off < 512; off <<= 1) {
        int t = (tid >= off) ? s[tid - off] : 0;
        __syncthreads();
        s[tid] += t;
        __syncthreads();
    }
    g_boff[tid] = s[tid] - v;
}

__global__ void k_finalize(int n, int E) {
    int i = blockIdx.x * blockDim.x + threadIdx.x;
    if (i >= n) return;
    int r = g_rowp[i] + g_boff[(i >> 8) & 511];
    g_rowp[i] = r;
    g_cursor[i] = r;
    if (i == 0) g_rowp[n] = E;
}

__global__ void k_scatter(const void* __restrict__ ei, int E, int n) {
    int e = blockIdx.x * blockDim.x + threadIdx.x;
    if (e >= E) return;
    int is64 = g_is64;
    int s = load_edge(ei, (size_t)e, is64);
    int d = load_edge(ei, (size_t)E + e, is64);
    if ((unsigned)s >= (unsigned)n || (unsigned)d >= (unsigned)n) return;
    int pos = atomicAdd(&g_cursor[d], 1);
    if ((unsigned)pos < (unsigned)NEDGES) g_col[pos] = s;
}

// ===========================================================================
// GEMM (row range [m0,m1)): H'[r] = dis[r] * ( f(X + bias_in)[r] @ W )
// ===========================================================================
__global__ void __launch_bounds__(128)
k_gemm128(const float* __restrict__ X, const float* __restrict__ W,
          float* __restrict__ H, const float* __restrict__ bias_in,
          int relu_in, int m0, int m1)
{
    __shared__ __align__(16) float Xs[32 * 128];

    int tid = threadIdx.x;
    int cg  = tid & 31;
    int rg  = tid >> 5;

    int t0 = m0 + blockIdx.x * 32;
    if (t0 >= m1) return;
    // full 32-row tiles guaranteed only if (m1-m0)%32==0 or last tile clipped:
    bool full = (t0 + 32 <= m1);

    #pragma unroll
    for (int i = 0; i < 8; i++) {
        int idx = (tid + i * 128) * 4;
        int row = t0 + (idx >> 7);
        float4 v = make_float4(0.f, 0.f, 0.f, 0.f);
        if (full || row < m1) v = *(const float4*)&X[(size_t)row * FDIM + (idx & 127)];
        if (bias_in) {
            int c = idx & 127;
            v.x += bias_in[c];     v.y += bias_in[c + 1];
            v.z += bias_in[c + 2]; v.w += bias_in[c + 3];
        }
        if (relu_in) {
            v.x = fmaxf(v.x, 0.f); v.y = fmaxf(v.y, 0.f);
            v.z = fmaxf(v.z, 0.f); v.w = fmaxf(v.w, 0.f);
        }
        *(float4*)&Xs[idx] = v;
    }
    __syncthreads();

    float acc[8][4];
    #pragma unroll
    for (int r = 0; r < 8; r++)
        #pragma unroll
        for (int c = 0; c < 4; c++) acc[r][c] = 0.f;

    const float4* Wp = (const float4*)W + cg;

    #pragma unroll 4
    for (int k = 0; k < 128; k += 2) {
        float2 xk[8];
        #pragma unroll
        for (int r = 0; r < 8; r++)
            xk[r] = *(const float2*)&Xs[(rg * 8 + r) * 128 + k];

        float4 w0 = __ldg(Wp + (size_t)(k + 0) * 32);
        float4 w1 = __ldg(Wp + (size_t)(k + 1) * 32);

        #pragma unroll
        for (int r = 0; r < 8; r++) {
            acc[r][0] = fmaf(xk[r].x, w0.x, acc[r][0]);
            acc[r][1] = fmaf(xk[r].x, w0.y, acc[r][1]);
            acc[r][2] = fmaf(xk[r].x, w0.z, acc[r][2]);
            acc[r][3] = fmaf(xk[r].x, w0.w, acc[r][3]);

            acc[r][0] = fmaf(xk[r].y, w1.x, acc[r][0]);
            acc[r][1] = fmaf(xk[r].y, w1.y, acc[r][1]);
            acc[r][2] = fmaf(xk[r].y, w1.z, acc[r][2]);
            acc[r][3] = fmaf(xk[r].y, w1.w, acc[r][3]);
        }
    }

    #pragma unroll
    for (int r = 0; r < 8; r++) {
        int row = t0 + rg * 8 + r;
        if (row < m1) {
            float ds = g_dis[row];
            *(float4*)&H[(size_t)row * FDIM + cg * 4] =
                make_float4(acc[r][0] * ds, acc[r][1] * ds,
                            acc[r][2] * ds, acc[r][3] * ds);
        }
    }
}

// ===========================================================================
// Layer-3 fused GEMM (rows [r0,r1)): G' = dis[r] * ( relu(X+b2) @ Wc )
// ===========================================================================
__global__ void __launch_bounds__(256)
k_gemm3(const float* __restrict__ X, const float* __restrict__ bias_in,
        float* __restrict__ G, int r0, int r1)
{
    __shared__ float Ws[128 * 40];
    __shared__ float xs[8][128];

    int tid  = threadIdx.x;
    int lane = tid & 31;
    int w    = tid >> 5;

    for (int i = tid; i < 128 * 40; i += 256) Ws[i] = g_Wc[i];
    __syncthreads();

    int col2 = 32 + (lane & 7);
    int nwarps = gridDim.x * 8;

    for (int r = r0 + blockIdx.x * 8 + w; r < r1; r += nwarps) {
        float4 v = *(const float4*)&X[(size_t)r * FDIM + lane * 4];
        int c = lane * 4;
        v.x += bias_in[c];     v.y += bias_in[c + 1];
        v.z += bias_in[c + 2]; v.w += bias_in[c + 3];
        v.x = fmaxf(v.x, 0.f); v.y = fmaxf(v.y, 0.f);
        v.z = fmaxf(v.z, 0.f); v.w = fmaxf(v.w, 0.f);
        *(float4*)&xs[w][lane * 4] = v;
        __syncwarp();

        float acc0 = 0.f, acc1 = 0.f;
        #pragma unroll 8
        for (int k = 0; k < 128; k++) {
            float xv = xs[w][k];
            acc0 = fmaf(xv, Ws[k * 40 + lane], acc0);
            acc1 = fmaf(xv, Ws[k * 40 + col2], acc1);
        }
        float ds = g_dis[r];
        G[(size_t)r * 40 + lane] = acc0 * ds;
        if (lane < 8)
            G[(size_t)r * 40 + 32 + lane] = acc1 * ds;
        __syncwarp();
    }
}

// ===========================================================================
// Aggregation (nodes [n0,n1)): A[d] = dis[d]*(H'[d] + sum H'[s])
// ===========================================================================
__global__ void __launch_bounds__(256)
k_agg(const float* __restrict__ H, float* __restrict__ A,
      int n0, int n1, int n, int E)
{
    int node = n0 + ((blockIdx.x * blockDim.x + threadIdx.x) >> 5);
    int lane = threadIdx.x & 31;
    if (node >= n1) return;

    float di = g_dis[node];
    int beg = g_rowp[node];
    int end = g_rowp[node + 1];
    if (beg < 0) beg = 0;
    if (end > E) end = E;

    float4 acc = *(const float4*)&H[(size_t)node * FDIM + lane * 4];

    int e = beg;
    for (; e + 4 <= end; e += 4) {
        int s0 = g_col[e];
        int s1 = g_col[e + 1];
        int s2 = g_col[e + 2];
        int s3 = g_col[e + 3];
        if ((unsigned)s0 >= (unsigned)n) s0 = 0;
        if ((unsigned)s1 >= (unsigned)n) s1 = 0;
        if ((unsigned)s2 >= (unsigned)n) s2 = 0;
        if ((unsigned)s3 >= (unsigned)n) s3 = 0;
        float4 v0 = *(const float4*)&H[(size_t)s0 * FDIM + lane * 4];
        float4 v1 = *(const float4*)&H[(size_t)s1 * FDIM + lane * 4];
        float4 v2 = *(const float4*)&H[(size_t)s2 * FDIM + lane * 4];
        float4 v3 = *(const float4*)&H[(size_t)s3 * FDIM + lane * 4];
        acc.x += v0.x; acc.y += v0.y; acc.z += v0.z; acc.w += v0.w;
        acc.x += v1.x; acc.y += v1.y; acc.z += v1.z; acc.w += v1.w;
        acc.x += v2.x; acc.y += v2.y; acc.z += v2.z; acc.w += v2.w;
        acc.x += v3.x; acc.y += v3.y; acc.z += v3.z; acc.w += v3.w;
    }
    for (; e < end; e++) {
        int s0 = g_col[e];
        if ((unsigned)s0 >= (unsigned)n) s0 = 0;
        float4 v0 = *(const float4*)&H[(size_t)s0 * FDIM + lane * 4];
        acc.x += v0.x; acc.y += v0.y; acc.z += v0.z; acc.w += v0.w;
    }

    acc.x *= di; acc.y *= di; acc.z *= di; acc.w *= di;
    *(float4*)&A[(size_t)node * FDIM + lane * 4] = acc;
}

// ===========================================================================
// Layer-3 aggregation (40-wide): OUT[d] = dis[d]*(G'[d] + sum G'[s]) + bc
// ===========================================================================
__global__ void __launch_bounds__(256)
k_agg40(const float* __restrict__ G, float* __restrict__ OUT, int n, int E)
{
    int hw = (blockIdx.x * blockDim.x + threadIdx.x) >> 4;
    int l  = threadIdx.x & 15;
    if (hw >= n) return;
    bool act = l < 10;
    int  c   = l * 4;

    float di = g_dis[hw];
    int beg = g_rowp[hw];
    int end = g_rowp[hw + 1];
    if (beg < 0) beg = 0;
    if (end > E) end = E;

    float4 acc = make_float4(0.f, 0.f, 0.f, 0.f);
    if (act) acc = *(const float4*)&G[(size_t)hw * 40 + c];

    int e = beg;
    for (; e + 4 <= end; e += 4) {
        int s0 = g_col[e];
        int s1 = g_col[e + 1];
        int s2 = g_col[e + 2];
        int s3 = g_col[e + 3];
        if ((unsigned)s0 >= (unsigned)n) s0 = 0;
        if ((unsigned)s1 >= (unsigned)n) s1 = 0;
        if ((unsigned)s2 >= (unsigned)n) s2 = 0;
        if ((unsigned)s3 >= (unsigned)n) s3 = 0;
        if (act) {
            float4 v0 = *(const float4*)&G[(size_t)s0 * 40 + c];
            float4 v1 = *(const float4*)&G[(size_t)s1 * 40 + c];
            float4 v2 = *(const float4*)&G[(size_t)s2 * 40 + c];
            float4 v3 = *(const float4*)&G[(size_t)s3 * 40 + c];
            acc.x += v0.x; acc.y += v0.y; acc.z += v0.z; acc.w += v0.w;
            acc.x += v1.x; acc.y += v1.y; acc.z += v1.z; acc.w += v1.w;
            acc.x += v2.x; acc.y += v2.y; acc.z += v2.z; acc.w += v2.w;
            acc.x += v3.x; acc.y += v3.y; acc.z += v3.z; acc.w += v3.w;
        }
    }
    for (; e < end; e++) {
        int s0 = g_col[e];
        if ((unsigned)s0 >= (unsigned)n) s0 = 0;
        if (act) {
            float4 v0 = *(const float4*)&G[(size_t)s0 * 40 + c];
            acc.x += v0.x; acc.y += v0.y; acc.z += v0.z; acc.w += v0.w;
        }
    }

    if (act) {
        acc.x = fmaf(acc.x, di, g_bc[c]);
        acc.y = fmaf(acc.y, di, g_bc[c + 1]);
        acc.z = fmaf(acc.z, di, g_bc[c + 2]);
        acc.w = fmaf(acc.w, di, g_bc[c + 3]);
        *(float4*)&OUT[(size_t)hw * 40 + c] = acc;
    }
}

// ===========================================================================
extern "C" void kernel_launch(void* const* d_in, const int* in_sizes, int n_in,
                              void* d_out, int out_size)
{
    const float* x  = (const float*)d_in[0];
    const void*  ei = d_in[1];
    const float* W1 = (const float*)d_in[2];
    const float* b1 = (const float*)d_in[3];
    const float* W2 = (const float*)d_in[4];
    const float* b2 = (const float*)d_in[5];
    const float* W3 = (const float*)d_in[6];
    const float* b3 = (const float*)d_in[7];
    const float* Wl = (const float*)d_in[8];
    const float* bl = (const float*)d_in[9];
    float* out = (float*)d_out;

    int N = in_sizes[0] / FDIM;
    int E = in_sizes[1] / 2;
    if (N > NNODES) N = NNODES;
    if (E > NEDGES) E = NEDGES;

    float *hp = nullptr, *h2p = nullptr, *ap = nullptr, *gp = nullptr;
    cudaGetSymbolAddress((void**)&hp,  g_h);
    cudaGetSymbolAddress((void**)&h2p, g_h2);
    cudaGetSymbolAddress((void**)&ap,  g_a);
    cudaGetSymbolAddress((void**)&gp,  g_g3);

    // One-time stream/event infra (created on first, uncaptured, call)
    static cudaStream_t s2 = nullptr;
    static cudaEvent_t evFork, evCsr, evA1[NC], evG2, evA2[NC], evG3;
    if (!s2) {
        cudaStreamCreateWithFlags(&s2, cudaStreamNonBlocking);
        cudaEventCreateWithFlags(&evFork, cudaEventDisableTiming);
        cudaEventCreateWithFlags(&evCsr,  cudaEventDisableTiming);
        cudaEventCreateWithFlags(&evG2,   cudaEventDisableTiming);
        cudaEventCreateWithFlags(&evG3,   cudaEventDisableTiming);
        for (int c = 0; c < NC; c++) {
            cudaEventCreateWithFlags(&evA1[c], cudaEventDisableTiming);
            cudaEventCreateWithFlags(&evA2[c], cudaEventDisableTiming);
        }
    }

    int nb = (N + 255) / 256;
    int eb = (E + 255) / 256;

    // Chunk bounds (32-aligned)
    int cs = (((N + NC - 1) / NC) + 31) & ~31;
    int c0[NC], c1[NC];
    for (int c = 0; c < NC; c++) {
        c0[c] = c * cs;
        c1[c] = (c + 1) * cs < N ? (c + 1) * cs : N;
        if (c0[c] > N) c0[c] = N;
    }

    // --- D: serial prefix (deg -> dis) ---
    k_init_flag <<<1, 1>>>();
    k_detect    <<<eb, 256>>>((const int*)ei, 2 * E);
    k_zero_deg  <<<nb, 256>>>(N);
    k_count_deg <<<eb, 256>>>(ei, E, N);
    k_dis       <<<nb, 256>>>(N);

    // Fork: s2 finishes CSR (scan/finalize/scatter) + fuseW, D runs gemm1
    cudaEventRecord(evFork, 0);
    cudaStreamWaitEvent(s2, evFork, 0);
    k_scan_block<<<nb, 256, 0, s2>>>(N);
    k_scan_spine<<<1, 512, 0, s2>>>(nb);
    k_finalize  <<<nb, 256, 0, s2>>>(N, E);
    k_scatter   <<<eb, 256, 0, s2>>>(ei, E, N);
    k_fuseW     <<<1, 256, 0, s2>>>(W3, Wl, b3, bl);
    cudaEventRecord(evCsr, s2);

    k_gemm128<<<(N + 31) / 32, 128>>>(x, W1, hp, nullptr, 0, 0, N);
    cudaStreamWaitEvent(0, evCsr, 0);    // agg needs CSR

    // --- Pipeline 1: agg1 (D) chunked, gemm2 (s2) trailing per chunk ---
    for (int c = 0; c < NC; c++) {
        int nn = c1[c] - c0[c];
        if (nn <= 0) continue;
        k_agg<<<(nn * 32 + 255) / 256, 256>>>(hp, ap, c0[c], c1[c], N, E);
        cudaEventRecord(evA1[c], 0);
        cudaStreamWaitEvent(s2, evA1[c], 0);
        k_gemm128<<<(nn + 31) / 32, 128, 0, s2>>>(ap, W2, h2p, b1, 1, c0[c], c1[c]);
    }
    cudaEventRecord(evG2, s2);
    cudaStreamWaitEvent(0, evG2, 0);     // agg2 gathers from all of H2

    // --- Pipeline 2: agg2 (D) chunked, gemm3 (s2) trailing per chunk ---
    for (int c = 0; c < NC; c++) {
        int nn = c1[c] - c0[c];
        if (nn <= 0) continue;
        k_agg<<<(nn * 32 + 255) / 256, 256>>>(h2p, ap, c0[c], c1[c], N, E);
        cudaEventRecord(evA2[c], 0);
        cudaStreamWaitEvent(s2, evA2[c], 0);
        k_gemm3<<<1024, 256, 0, s2>>>(ap, b2, gp, c0[c], c1[c]);
    }
    cudaEventRecord(evG3, s2);
    cudaStreamWaitEvent(0, evG3, 0);     // agg40 gathers from all of G

    // --- Final: 40-wide aggregation + bias -> out (D) ---
    k_agg40<<<(N * 16 + 255) / 256, 256>>>(gp, out, N, E);
}

// round 11
// speedup vs baseline: 1.1601x; 1.1601x over previous
#include <cuda_runtime.h>
#include <cuda_fp16.h>
#include <cstdint>

#define NNODES 100000
#define NEDGES 1600000
#define FDIM   128

// Scratch (device globals — no allocation allowed anywhere)
__device__ __half g_h [(size_t)NNODES * FDIM]; // dis-scaled messages (fp16)
__device__ float  g_a [(size_t)NNODES * FDIM]; // aggregated features (fp32)
__device__ __half g_g3[(size_t)NNODES * 40];   // layer-3 fused messages (fp16)
__device__ float  g_dis[NNODES];               // (deg+1)^{-1/2}
__device__ int    g_deg[NNODES];
__device__ int    g_rowp[NNODES + 1];
__device__ int    g_cursor[NNODES];
__device__ int    g_col[NEDGES];
__device__ int    g_bsum[512];
__device__ int    g_boff[512];
__device__ int    g_is64;
__device__ float  g_Wc[128 * 40];              // W3 @ Wl
__device__ float  g_bc[40];                    // b3 @ Wl + bl

// ===========================================================================
// Edge dtype detection
// ===========================================================================
__global__ void k_init_flag() { g_is64 = 1; }

__global__ void k_detect(const int* __restrict__ p, int twoE) {
    int i = blockIdx.x * blockDim.x + threadIdx.x;
    int idx = 2 * i + 1;
    if (idx < twoE && p[idx] != 0) g_is64 = 0;
}

__device__ __forceinline__ int load_edge(const void* ei, size_t idx, int is64) {
    if (is64) return (int)((const long long*)ei)[idx];
    return ((const int*)ei)[idx];
}

// ===========================================================================
// Weight fusion: Wc = W3 @ Wl, bc = b3 @ Wl + bl
// ===========================================================================
__global__ void __launch_bounds__(256) k_fuseW(const float* __restrict__ W3,
                                               const float* __restrict__ Wl,
                                               const float* __restrict__ b3,
                                               const float* __restrict__ bl)
{
    __shared__ float Wls[128 * 40];
    int tid = threadIdx.x;
    for (int i = tid; i < 128 * 40; i += 256) Wls[i] = Wl[i];
    __syncthreads();

    for (int o = tid; o < 128 * 40; o += 256) {
        int i = o / 40, n = o % 40;
        float s = 0.f;
        #pragma unroll 8
        for (int k = 0; k < 128; k++)
            s = fmaf(W3[(size_t)i * FDIM + k], Wls[k * 40 + n], s);
        g_Wc[o] = s;
    }
    if (tid < 40) {
        float s = bl[tid];
        #pragma unroll 8
        for (int k = 0; k < 128; k++)
            s = fmaf(b3[k], Wls[k * 40 + tid], s);
        g_bc[tid] = s;
    }
}

// ===========================================================================
// CSR build
// ===========================================================================
__global__ void k_zero_deg(int n) {
    int i = blockIdx.x * blockDim.x + threadIdx.x;
    if (i < n) g_deg[i] = 0;
}

__global__ void k_count_deg(const void* __restrict__ ei, int E, int n) {
    int e = blockIdx.x * blockDim.x + threadIdx.x;
    if (e >= E) return;
    int is64 = g_is64;
    int d = load_edge(ei, (size_t)E + e, is64);
    if ((unsigned)d < (unsigned)n) atomicAdd(&g_deg[d], 1);
}

__global__ void __launch_bounds__(256) k_scan_block(int n) {
    __shared__ int s[256];
    int tid = threadIdx.x;
    int i = blockIdx.x * 256 + tid;
    int v = (i < n) ? g_deg[i] : 0;
    s[tid] = v;
    __syncthreads();
    for (int off = 1; off < 256; off <<= 1) {
        int t = (tid >= off) ? s[tid - off] : 0;
        __syncthreads();
        s[tid] += t;
        __syncthreads();
    }
    if (i < n) g_rowp[i] = s[tid] - v;
    if (tid == 255 && blockIdx.x < 512) g_bsum[blockIdx.x] = s[255];
}

__global__ void __launch_bounds__(512) k_scan_spine(int nb) {
    __shared__ int s[512];
    int tid = threadIdx.x;
    int v = (tid < nb) ? g_bsum[tid] : 0;
    s[tid] = v;
    __syncthreads();
    for (int off = 1; off < 512; off <<= 1) {
        int t = (tid >= off) ? s[tid - off] : 0;
        __syncthreads();
        s[tid] += t;
        __syncthreads();
    }
    g_boff[tid] = s[tid] - v;
}

__global__ void k_finalize(int n, int E) {
    int i = blockIdx.x * blockDim.x + threadIdx.x;
    if (i >= n) return;
    int r = g_rowp[i] + g_boff[(i >> 8) & 511];
    g_rowp[i] = r;
    g_cursor[i] = r;
    g_dis[i] = rsqrtf((float)(g_deg[i] + 1));
    if (i == 0) g_rowp[n] = E;
}

__global__ void k_scatter(const void* __restrict__ ei, int E, int n) {
    int e = blockIdx.x * blockDim.x + threadIdx.x;
    if (e >= E) return;
    int is64 = g_is64;
    int s = load_edge(ei, (size_t)e, is64);
    int d = load_edge(ei, (size_t)E + e, is64);
    if ((unsigned)s >= (unsigned)n || (unsigned)d >= (unsigned)n) return;
    int pos = atomicAdd(&g_cursor[d], 1);
    if ((unsigned)pos < (unsigned)NEDGES) g_col[pos] = s;
}

// ===========================================================================
// GEMM: H'[M,128](fp16) = dis[row] * ( f(X + bias_in)[M,128] @ W[128,128] )
// ===========================================================================
__global__ void __launch_bounds__(128)
k_gemm128(const float* __restrict__ X, const float* __restrict__ W,
          __half* __restrict__ H, const float* __restrict__ bias_in,
          int relu_in, int M)
{
    __shared__ __align__(16) float Xs[32 * 128];

    int tid = threadIdx.x;
    int cg  = tid & 31;
    int rg  = tid >> 5;

    int t0 = blockIdx.x * 32;
    if (t0 >= M) return;

    #pragma unroll
    for (int i = 0; i < 8; i++) {
        int idx = (tid + i * 128) * 4;
        int row = t0 + (idx >> 7);
        float4 v = make_float4(0.f, 0.f, 0.f, 0.f);
        if (row < M) v = *(const float4*)&X[(size_t)row * FDIM + (idx & 127)];
        if (bias_in) {
            int c = idx & 127;
            v.x += bias_in[c];     v.y += bias_in[c + 1];
            v.z += bias_in[c + 2]; v.w += bias_in[c + 3];
        }
        if (relu_in) {
            v.x = fmaxf(v.x, 0.f); v.y = fmaxf(v.y, 0.f);
            v.z = fmaxf(v.z, 0.f); v.w = fmaxf(v.w, 0.f);
        }
        *(float4*)&Xs[idx] = v;
    }
    __syncthreads();

    float acc[8][4];
    #pragma unroll
    for (int r = 0; r < 8; r++)
        #pragma unroll
        for (int c = 0; c < 4; c++) acc[r][c] = 0.f;

    const float4* Wp = (const float4*)W + cg;

    #pragma unroll 4
    for (int k = 0; k < 128; k += 2) {
        float2 xk[8];
        #pragma unroll
        for (int r = 0; r < 8; r++)
            xk[r] = *(const float2*)&Xs[(rg * 8 + r) * 128 + k];

        float4 w0 = __ldg(Wp + (size_t)(k + 0) * 32);
        float4 w1 = __ldg(Wp + (size_t)(k + 1) * 32);

        #pragma unroll
        for (int r = 0; r < 8; r++) {
            acc[r][0] = fmaf(xk[r].x, w0.x, acc[r][0]);
            acc[r][1] = fmaf(xk[r].x, w0.y, acc[r][1]);
            acc[r][2] = fmaf(xk[r].x, w0.z, acc[r][2]);
            acc[r][3] = fmaf(xk[r].x, w0.w, acc[r][3]);

            acc[r][0] = fmaf(xk[r].y, w1.x, acc[r][0]);
            acc[r][1] = fmaf(xk[r].y, w1.y, acc[r][1]);
            acc[r][2] = fmaf(xk[r].y, w1.z, acc[r][2]);
            acc[r][3] = fmaf(xk[r].y, w1.w, acc[r][3]);
        }
    }

    #pragma unroll
    for (int r = 0; r < 8; r++) {
        int row = t0 + rg * 8 + r;
        if (row < M) {
            float ds = g_dis[row];
            union { __half2 h[2]; uint2 u; } cv;
            cv.h[0] = __floats2half2_rn(acc[r][0] * ds, acc[r][1] * ds);
            cv.h[1] = __floats2half2_rn(acc[r][2] * ds, acc[r][3] * ds);
            *(uint2*)&H[(size_t)row * FDIM + cg * 4] = cv.u;
        }
    }
}

// ===========================================================================
// Layer-3 fused GEMM: G'[M,40](fp16) = dis[r] * ( relu(X+b2) @ Wc[128,40] )
// ===========================================================================
__global__ void __launch_bounds__(256)
k_gemm3(const float* __restrict__ X, const float* __restrict__ bias_in,
        __half* __restrict__ G, int M)
{
    __shared__ float Ws[128 * 40];
    __shared__ float xs[8][128];

    int tid  = threadIdx.x;
    int lane = tid & 31;
    int w    = tid >> 5;

    for (int i = tid; i < 128 * 40; i += 256) Ws[i] = g_Wc[i];
    __syncthreads();

    int col2 = 32 + (lane & 7);
    int nwarps = gridDim.x * 8;

    for (int r = blockIdx.x * 8 + w; r < M; r += nwarps) {
        float4 v = *(const float4*)&X[(size_t)r * FDIM + lane * 4];
        int c = lane * 4;
        v.x += bias_in[c];     v.y += bias_in[c + 1];
        v.z += bias_in[c + 2]; v.w += bias_in[c + 3];
        v.x = fmaxf(v.x, 0.f); v.y = fmaxf(v.y, 0.f);
        v.z = fmaxf(v.z, 0.f); v.w = fmaxf(v.w, 0.f);
        *(float4*)&xs[w][lane * 4] = v;
        __syncwarp();

        float acc0 = 0.f, acc1 = 0.f;
        #pragma unroll 8
        for (int k = 0; k < 128; k++) {
            float xv = xs[w][k];
            acc0 = fmaf(xv, Ws[k * 40 + lane], acc0);
            acc1 = fmaf(xv, Ws[k * 40 + col2], acc1);
        }
        float ds = g_dis[r];
        G[(size_t)r * 40 + lane] = __float2half_rn(acc0 * ds);
        if (lane < 8)
            G[(size_t)r * 40 + 32 + lane] = __float2half_rn(acc1 * ds);
        __syncwarp();
    }
}

// ===========================================================================
// Aggregation (fp16 gather): HALF-warp (16 lanes) per dst node.
// Each lane covers 8 cols (16 B). A[d] = dis[d]*(H'[d] + sum H'[s])  (fp32 acc)
// ===========================================================================
__device__ __forceinline__ void acc_h8(float* a, uint4 v) {
    __half2* p = (__half2*)&v;
    float2 f0 = __half22float2(p[0]);
    float2 f1 = __half22float2(p[1]);
    float2 f2 = __half22float2(p[2]);
    float2 f3 = __half22float2(p[3]);
    a[0] += f0.x; a[1] += f0.y; a[2] += f1.x; a[3] += f1.y;
    a[4] += f2.x; a[5] += f2.y; a[6] += f3.x; a[7] += f3.y;
}

__global__ void __launch_bounds__(256)
k_agg(const __half* __restrict__ H, float* __restrict__ A, int n, int E)
{
    int node = (blockIdx.x * blockDim.x + threadIdx.x) >> 4;
    int hl   = threadIdx.x & 15;
    if (node >= n) return;

    float di = g_dis[node];
    int beg = g_rowp[node];
    int end = g_rowp[node + 1];
    if (beg < 0) beg = 0;
    if (end > E) end = E;

    float a[8];
    {
        uint4 sv = __ldg((const uint4*)(H + (size_t)node * FDIM) + hl);
        __half2* p = (__half2*)&sv;
        float2 f0 = __half22float2(p[0]);
        float2 f1 = __half22float2(p[1]);
        float2 f2 = __half22float2(p[2]);
        float2 f3 = __half22float2(p[3]);
        a[0] = f0.x; a[1] = f0.y; a[2] = f1.x; a[3] = f1.y;
        a[4] = f2.x; a[5] = f2.y; a[6] = f3.x; a[7] = f3.y;
    }

    int e = beg;
    for (; e + 2 <= end; e += 2) {
        int s0 = g_col[e];
        int s1 = g_col[e + 1];
        if ((unsigned)s0 >= (unsigned)n) s0 = 0;
        if ((unsigned)s1 >= (unsigned)n) s1 = 0;
        uint4 v0 = __ldg((const uint4*)(H + (size_t)s0 * FDIM) + hl);
        uint4 v1 = __ldg((const uint4*)(H + (size_t)s1 * FDIM) + hl);
        acc_h8(a, v0);
        acc_h8(a, v1);
    }
    if (e < end) {
        int s0 = g_col[e];
        if ((unsigned)s0 >= (unsigned)n) s0 = 0;
        uint4 v0 = __ldg((const uint4*)(H + (size_t)s0 * FDIM) + hl);
        acc_h8(a, v0);
    }

    float* Ar = A + (size_t)node * FDIM + hl * 8;
    *(float4*)Ar       = make_float4(a[0] * di, a[1] * di, a[2] * di, a[3] * di);
    *(float4*)(Ar + 4) = make_float4(a[4] * di, a[5] * di, a[6] * di, a[7] * di);
}

// ===========================================================================
// Layer-3 aggregation (fp16, 40-wide): OUT = dis[d]*(G'[d] + sum G'[s]) + bc
// 16 lanes per node; lanes 0..9 each cover 4 cols (8 B).
// ===========================================================================
__global__ void __launch_bounds__(256)
k_agg40(const __half* __restrict__ G, float* __restrict__ OUT, int n, int E)
{
    int hw = (blockIdx.x * blockDim.x + threadIdx.x) >> 4;
    int l  = threadIdx.x & 15;
    if (hw >= n) return;
    bool act = l < 10;
    int  c   = l * 4;

    float di = g_dis[hw];
    int beg = g_rowp[hw];
    int end = g_rowp[hw + 1];
    if (beg < 0) beg = 0;
    if (end > E) end = E;

    float a0 = 0.f, a1 = 0.f, a2 = 0.f, a3 = 0.f;
    if (act) {
        uint2 sv = __ldg((const uint2*)(G + (size_t)hw * 40) + l);
        __half2* p = (__half2*)&sv;
        float2 f0 = __half22float2(p[0]);
        float2 f1 = __half22float2(p[1]);
        a0 = f0.x; a1 = f0.y; a2 = f1.x; a3 = f1.y;
    }

    int e = beg;
    for (; e + 2 <= end; e += 2) {
        int s0 = g_col[e];
        int s1 = g_col[e + 1];
        if ((unsigned)s0 >= (unsigned)n) s0 = 0;
        if ((unsigned)s1 >= (unsigned)n) s1 = 0;
        if (act) {
            uint2 v0 = __ldg((const uint2*)(G + (size_t)s0 * 40) + l);
            uint2 v1 = __ldg((const uint2*)(G + (size_t)s1 * 40) + l);
            __half2* p0 = (__half2*)&v0;
            __half2* p1 = (__half2*)&v1;
            float2 f;
            f = __half22float2(p0[0]); a0 += f.x; a1 += f.y;
            f = __half22float2(p0[1]); a2 += f.x; a3 += f.y;
            f = __half22float2(p1[0]); a0 += f.x; a1 += f.y;
            f = __half22float2(p1[1]); a2 += f.x; a3 += f.y;
        }
    }
    if (e < end) {
        int s0 = g_col[e];
        if ((unsigned)s0 >= (unsigned)n) s0 = 0;
        if (act) {
            uint2 v0 = __ldg((const uint2*)(G + (size_t)s0 * 40) + l);
            __half2* p0 = (__half2*)&v0;
            float2 f;
            f = __half22float2(p0[0]); a0 += f.x; a1 += f.y;
            f = __half22float2(p0[1]); a2 += f.x; a3 += f.y;
        }
    }

    if (act) {
        float4 o;
        o.x = fmaf(a0, di, g_bc[c]);
        o.y = fmaf(a1, di, g_bc[c + 1]);
        o.z = fmaf(a2, di, g_bc[c + 2]);
        o.w = fmaf(a3, di, g_bc[c + 3]);
        *(float4*)&OUT[(size_t)hw * 40 + c] = o;
    }
}

// ===========================================================================
extern "C" void kernel_launch(void* const* d_in, const int* in_sizes, int n_in,
                              void* d_out, int out_size)
{
    const float* x  = (const float*)d_in[0];
    const void*  ei = d_in[1];
    const float* W1 = (const float*)d_in[2];
    const float* b1 = (const float*)d_in[3];
    const float* W2 = (const float*)d_in[4];
    const float* b2 = (const float*)d_in[5];
    const float* W3 = (const float*)d_in[6];
    const float* b3 = (const float*)d_in[7];
    const float* Wl = (const float*)d_in[8];
    const float* bl = (const float*)d_in[9];
    float* out = (float*)d_out;

    int N = in_sizes[0] / FDIM;
    int E = in_sizes[1] / 2;
    if (N > NNODES) N = NNODES;
    if (E > NEDGES) E = NEDGES;

    __half *hp = nullptr, *gp = nullptr;
    float  *ap = nullptr;
    cudaGetSymbolAddress((void**)&hp, g_h);
    cudaGetSymbolAddress((void**)&ap, g_a);
    cudaGetSymbolAddress((void**)&gp, g_g3);

    int nb = (N + 255) / 256;
    int eb = (E + 255) / 256;
    int gemm_blocks = (N + 31) / 32;
    int agg_blocks  = (N * 16 + 255) / 256;   // 16 lanes per node

    // --- CSR build + normalization ---
    k_init_flag <<<1, 1>>>();
    k_detect    <<<eb, 256>>>((const int*)ei, 2 * E);
    k_zero_deg  <<<nb, 256>>>(N);
    k_count_deg <<<eb, 256>>>(ei, E, N);
    k_scan_block<<<nb, 256>>>(N);
    k_scan_spine<<<1, 512>>>(nb);
    k_finalize  <<<nb, 256>>>(N, E);
    k_scatter   <<<eb, 256>>>(ei, E, N);
    k_fuseW     <<<1, 256>>>(W3, Wl, b3, bl);

    // Layer 1
    k_gemm128<<<gemm_blocks, 128>>>(x, W1, hp, nullptr, 0, N);
    k_agg    <<<agg_blocks, 256>>>(hp, ap, N, E);

    // Layer 2
    k_gemm128<<<gemm_blocks, 128>>>(ap, W2, hp, b1, 1, N);
    k_agg    <<<agg_blocks, 256>>>(hp, ap, N, E);

    // Layer 3 fused with head
    k_gemm3 <<<2048, 256>>>(ap, b2, gp, N);
    k_agg40 <<<agg_blocks, 256>>>(gp, out, N, E);
}

// round 12
// speedup vs baseline: 1.2563x; 1.0829x over previous
#include <cuda_runtime.h>
#include <cuda_fp16.h>
#include <cstdint>

#define NNODES 100000
#define NEDGES 1600000
#define FDIM   128

// Scratch (device globals — no allocation allowed anywhere)
__device__ __half g_h [(size_t)NNODES * FDIM]; // dis-scaled messages (fp16)
__device__ float  g_a [(size_t)NNODES * FDIM]; // aggregated features (fp32)
__device__ __half g_g3[(size_t)NNODES * 40];   // layer-3 fused messages (fp16)
__device__ float  g_dis[NNODES];               // (deg+1)^{-1/2}
__device__ int    g_deg[NNODES];
__device__ int    g_rowp[NNODES + 1];
__device__ int    g_cursor[NNODES];
__device__ int    g_col[NEDGES];
__device__ int    g_bsum[512];
__device__ int    g_boff[512];
__device__ int    g_is64;
__device__ float  g_Wc[128 * 40];              // W3 @ Wl
__device__ float  g_bc[40];                    // b3 @ Wl + bl

// ===========================================================================
// Boot: zero deg + set dtype flag
// ===========================================================================
__global__ void k_boot(int n) {
    int i = blockIdx.x * blockDim.x + threadIdx.x;
    if (i < n) g_deg[i] = 0;
    if (i == 0) g_is64 = 1;
}

// Prefix-only dtype detection: int64(small values) => all odd int32 words zero.
// 256 odd words of random int32 node ids are all-zero with prob ~1e-1280.
__global__ void k_detect(const int* __restrict__ p, int twoE) {
    int idx = 2 * threadIdx.x + 1;
    if (idx < twoE && p[idx] != 0) g_is64 = 0;
}

__device__ __forceinline__ int load_edge(const void* ei, size_t idx, int is64) {
    if (is64) return (int)((const long long*)ei)[idx];
    return ((const int*)ei)[idx];
}

// ===========================================================================
// Weight fusion: Wc = W3 @ Wl, bc = b3 @ Wl + bl
// ===========================================================================
__global__ void __launch_bounds__(256) k_fuseW(const float* __restrict__ W3,
                                               const float* __restrict__ Wl,
                                               const float* __restrict__ b3,
                                               const float* __restrict__ bl)
{
    __shared__ float Wls[128 * 40];
    int tid = threadIdx.x;
    for (int i = tid; i < 128 * 40; i += 256) Wls[i] = Wl[i];
    __syncthreads();

    for (int o = tid; o < 128 * 40; o += 256) {
        int i = o / 40, n = o % 40;
        float s = 0.f;
        #pragma unroll 8
        for (int k = 0; k < 128; k++)
            s = fmaf(W3[(size_t)i * FDIM + k], Wls[k * 40 + n], s);
        g_Wc[o] = s;
    }
    if (tid < 40) {
        float s = bl[tid];
        #pragma unroll 8
        for (int k = 0; k < 128; k++)
            s = fmaf(b3[k], Wls[k * 40 + tid], s);
        g_bc[tid] = s;
    }
}

// ===========================================================================
// CSR build
// ===========================================================================
__global__ void k_count_deg(const void* __restrict__ ei, int E, int n) {
    int e = blockIdx.x * blockDim.x + threadIdx.x;
    if (e >= E) return;
    int is64 = g_is64;
    int d = load_edge(ei, (size_t)E + e, is64);
    if ((unsigned)d < (unsigned)n) atomicAdd(&g_deg[d], 1);
}

__global__ void k_dis(int n) {
    int i = blockIdx.x * blockDim.x + threadIdx.x;
    if (i < n) g_dis[i] = rsqrtf((float)(g_deg[i] + 1));
}

__global__ void __launch_bounds__(256) k_scan_block(int n) {
    __shared__ int s[256];
    int tid = threadIdx.x;
    int i = blockIdx.x * 256 + tid;
    int v = (i < n) ? g_deg[i] : 0;
    s[tid] = v;
    __syncthreads();
    for (int off = 1; off < 256; off <<= 1) {
        int t = (tid >= off) ? s[tid - off] : 0;
        __syncthreads();
        s[tid] += t;
        __syncthreads();
    }
    if (i < n) g_rowp[i] = s[tid] - v;
    if (tid == 255 && blockIdx.x < 512) g_bsum[blockIdx.x] = s[255];
}

__global__ void __launch_bounds__(512) k_scan_spine(int nb) {
    __shared__ int s[512];
    int tid = threadIdx.x;
    int v = (tid < nb) ? g_bsum[tid] : 0;
    s[tid] = v;
    __syncthreads();
    for (int off = 1; off < 512; off <<= 1) {
        int t = (tid >= off) ? s[tid - off] : 0;
        __syncthreads();
        s[tid] += t;
        __syncthreads();
    }
    g_boff[tid] = s[tid] - v;
}

__global__ void k_finalize(int n, int E) {
    int i = blockIdx.x * blockDim.x + threadIdx.x;
    if (i >= n) return;
    int r = g_rowp[i] + g_boff[(i >> 8) & 511];
    g_rowp[i] = r;
    g_cursor[i] = r;
    if (i == 0) g_rowp[n] = E;
}

__global__ void k_scatter(const void* __restrict__ ei, int E, int n) {
    int e = blockIdx.x * blockDim.x + threadIdx.x;
    if (e >= E) return;
    int is64 = g_is64;
    int s = load_edge(ei, (size_t)e, is64);
    int d = load_edge(ei, (size_t)E + e, is64);
    if ((unsigned)s >= (unsigned)n || (unsigned)d >= (unsigned)n) return;
    int pos = atomicAdd(&g_cursor[d], 1);
    if ((unsigned)pos < (unsigned)NEDGES) g_col[pos] = s;
}

// ===========================================================================
// GEMM (4-k inner, R8-measured): H'(fp16) = dis[row] * ( f(X+bias) @ W )
// ===========================================================================
__global__ void __launch_bounds__(128)
k_gemm128(const float* __restrict__ X, const float* __restrict__ W,
          __half* __restrict__ H, const float* __restrict__ bias_in,
          int relu_in, int M)
{
    __shared__ __align__(16) float Xs[32 * 128];

    int tid = threadIdx.x;
    int cg  = tid & 31;
    int rg  = tid >> 5;

    int t0 = blockIdx.x * 32;
    if (t0 >= M) return;

    #pragma unroll
    for (int i = 0; i < 8; i++) {
        int idx = (tid + i * 128) * 4;
        int row = t0 + (idx >> 7);
        float4 v = make_float4(0.f, 0.f, 0.f, 0.f);
        if (row < M) v = *(const float4*)&X[(size_t)row * FDIM + (idx & 127)];
        if (bias_in) {
            int c = idx & 127;
            v.x += bias_in[c];     v.y += bias_in[c + 1];
            v.z += bias_in[c + 2]; v.w += bias_in[c + 3];
        }
        if (relu_in) {
            v.x = fmaxf(v.x, 0.f); v.y = fmaxf(v.y, 0.f);
            v.z = fmaxf(v.z, 0.f); v.w = fmaxf(v.w, 0.f);
        }
        *(float4*)&Xs[idx] = v;
    }
    __syncthreads();

    float acc[8][4];
    #pragma unroll
    for (int r = 0; r < 8; r++)
        #pragma unroll
        for (int c = 0; c < 4; c++) acc[r][c] = 0.f;

    const float4* Wp = (const float4*)W + cg;

    #pragma unroll 4
    for (int k = 0; k < 128; k += 4) {
        float4 xk[8];
        #pragma unroll
        for (int r = 0; r < 8; r++)
            xk[r] = *(const float4*)&Xs[(rg * 8 + r) * 128 + k];

        float4 w0 = __ldg(Wp + (size_t)(k + 0) * 32);
        float4 w1 = __ldg(Wp + (size_t)(k + 1) * 32);
        float4 w2 = __ldg(Wp + (size_t)(k + 2) * 32);
        float4 w3 = __ldg(Wp + (size_t)(k + 3) * 32);

        #pragma unroll
        for (int r = 0; r < 8; r++) {
            acc[r][0] = fmaf(xk[r].x, w0.x, acc[r][0]);
            acc[r][1] = fmaf(xk[r].x, w0.y, acc[r][1]);
            acc[r][2] = fmaf(xk[r].x, w0.z, acc[r][2]);
            acc[r][3] = fmaf(xk[r].x, w0.w, acc[r][3]);

            acc[r][0] = fmaf(xk[r].y, w1.x, acc[r][0]);
            acc[r][1] = fmaf(xk[r].y, w1.y, acc[r][1]);
            acc[r][2] = fmaf(xk[r].y, w1.z, acc[r][2]);
            acc[r][3] = fmaf(xk[r].y, w1.w, acc[r][3]);

            acc[r][0] = fmaf(xk[r].z, w2.x, acc[r][0]);
            acc[r][1] = fmaf(xk[r].z, w2.y, acc[r][1]);
            acc[r][2] = fmaf(xk[r].z, w2.z, acc[r][2]);
            acc[r][3] = fmaf(xk[r].z, w2.w, acc[r][3]);

            acc[r][0] = fmaf(xk[r].w, w3.x, acc[r][0]);
            acc[r][1] = fmaf(xk[r].w, w3.y, acc[r][1]);
            acc[r][2] = fmaf(xk[r].w, w3.z, acc[r][2]);
            acc[r][3] = fmaf(xk[r].w, w3.w, acc[r][3]);
        }
    }

    #pragma unroll
    for (int r = 0; r < 8; r++) {
        int row = t0 + rg * 8 + r;
        if (row < M) {
            float ds = g_dis[row];
            union { __half2 h[2]; uint2 u; } cv;
            cv.h[0] = __floats2half2_rn(acc[r][0] * ds, acc[r][1] * ds);
            cv.h[1] = __floats2half2_rn(acc[r][2] * ds, acc[r][3] * ds);
            *(uint2*)&H[(size_t)row * FDIM + cg * 4] = cv.u;
        }
    }
}

// ===========================================================================
// Layer-3 fused GEMM: G'(fp16) = dis[r] * ( relu(X+b2) @ Wc[128,40] )
// ===========================================================================
__global__ void __launch_bounds__(256)
k_gemm3(const float* __restrict__ X, const float* __restrict__ bias_in,
        __half* __restrict__ G, int M)
{
    __shared__ float Ws[128 * 40];
    __shared__ float xs[8][128];

    int tid  = threadIdx.x;
    int lane = tid & 31;
    int w    = tid >> 5;

    for (int i = tid; i < 128 * 40; i += 256) Ws[i] = g_Wc[i];
    __syncthreads();

    int col2 = 32 + (lane & 7);
    int nwarps = gridDim.x * 8;

    for (int r = blockIdx.x * 8 + w; r < M; r += nwarps) {
        float4 v = *(const float4*)&X[(size_t)r * FDIM + lane * 4];
        int c = lane * 4;
        v.x += bias_in[c];     v.y += bias_in[c + 1];
        v.z += bias_in[c + 2]; v.w += bias_in[c + 3];
        v.x = fmaxf(v.x, 0.f); v.y = fmaxf(v.y, 0.f);
        v.z = fmaxf(v.z, 0.f); v.w = fmaxf(v.w, 0.f);
        *(float4*)&xs[w][lane * 4] = v;
        __syncwarp();

        float acc0 = 0.f, acc1 = 0.f;
        #pragma unroll 8
        for (int k = 0; k < 128; k++) {
            float xv = xs[w][k];
            acc0 = fmaf(xv, Ws[k * 40 + lane], acc0);
            acc1 = fmaf(xv, Ws[k * 40 + col2], acc1);
        }
        float ds = g_dis[r];
        G[(size_t)r * 40 + lane] = __float2half_rn(acc0 * ds);
        if (lane < 8)
            G[(size_t)r * 40 + 32 + lane] = __float2half_rn(acc1 * ds);
        __syncwarp();
    }
}

// ===========================================================================
// Aggregation (fp16 gather): 16 lanes per dst node, fp32 accumulate.
// ===========================================================================
__device__ __forceinline__ void acc_h8(float* a, uint4 v) {
    __half2* p = (__half2*)&v;
    float2 f0 = __half22float2(p[0]);
    float2 f1 = __half22float2(p[1]);
    float2 f2 = __half22float2(p[2]);
    float2 f3 = __half22float2(p[3]);
    a[0] += f0.x; a[1] += f0.y; a[2] += f1.x; a[3] += f1.y;
    a[4] += f2.x; a[5] += f2.y; a[6] += f3.x; a[7] += f3.y;
}

__global__ void __launch_bounds__(256)
k_agg(const __half* __restrict__ H, float* __restrict__ A, int n, int E)
{
    int node = (blockIdx.x * blockDim.x + threadIdx.x) >> 4;
    int hl   = threadIdx.x & 15;
    if (node >= n) return;

    float di = g_dis[node];
    int beg = g_rowp[node];
    int end = g_rowp[node + 1];
    if (beg < 0) beg = 0;
    if (end > E) end = E;

    float a[8];
    {
        uint4 sv = __ldg((const uint4*)(H + (size_t)node * FDIM) + hl);
        __half2* p = (__half2*)&sv;
        float2 f0 = __half22float2(p[0]);
        float2 f1 = __half22float2(p[1]);
        float2 f2 = __half22float2(p[2]);
        float2 f3 = __half22float2(p[3]);
        a[0] = f0.x; a[1] = f0.y; a[2] = f1.x; a[3] = f1.y;
        a[4] = f2.x; a[5] = f2.y; a[6] = f3.x; a[7] = f3.y;
    }

    int e = beg;
    for (; e + 2 <= end; e += 2) {
        int s0 = g_col[e];
        int s1 = g_col[e + 1];
        if ((unsigned)s0 >= (unsigned)n) s0 = 0;
        if ((unsigned)s1 >= (unsigned)n) s1 = 0;
        uint4 v0 = __ldg((const uint4*)(H + (size_t)s0 * FDIM) + hl);
        uint4 v1 = __ldg((const uint4*)(H + (size_t)s1 * FDIM) + hl);
        acc_h8(a, v0);
        acc_h8(a, v1);
    }
    if (e < end) {
        int s0 = g_col[e];
        if ((unsigned)s0 >= (unsigned)n) s0 = 0;
        uint4 v0 = __ldg((const uint4*)(H + (size_t)s0 * FDIM) + hl);
        acc_h8(a, v0);
    }

    float* Ar = A + (size_t)node * FDIM + hl * 8;
    *(float4*)Ar       = make_float4(a[0] * di, a[1] * di, a[2] * di, a[3] * di);
    *(float4*)(Ar + 4) = make_float4(a[4] * di, a[5] * di, a[6] * di, a[7] * di);
}

// ===========================================================================
// Layer-3 aggregation (fp16, 40-wide): OUT = dis[d]*(G'[d] + sum G'[s]) + bc
// ===========================================================================
__global__ void __launch_bounds__(256)
k_agg40(const __half* __restrict__ G, float* __restrict__ OUT, int n, int E)
{
    int hw = (blockIdx.x * blockDim.x + threadIdx.x) >> 4;
    int l  = threadIdx.x & 15;
    if (hw >= n) return;
    bool act = l < 10;
    int  c   = l * 4;

    float di = g_dis[hw];
    int beg = g_rowp[hw];
    int end = g_rowp[hw + 1];
    if (beg < 0) beg = 0;
    if (end > E) end = E;

    float a0 = 0.f, a1 = 0.f, a2 = 0.f, a3 = 0.f;
    if (act) {
        uint2 sv = __ldg((const uint2*)(G + (size_t)hw * 40) + l);
        __half2* p = (__half2*)&sv;
        float2 f0 = __half22float2(p[0]);
        float2 f1 = __half22float2(p[1]);
        a0 = f0.x; a1 = f0.y; a2 = f1.x; a3 = f1.y;
    }

    int e = beg;
    for (; e + 2 <= end; e += 2) {
        int s0 = g_col[e];
        int s1 = g_col[e + 1];
        if ((unsigned)s0 >= (unsigned)n) s0 = 0;
        if ((unsigned)s1 >= (unsigned)n) s1 = 0;
        if (act) {
            uint2 v0 = __ldg((const uint2*)(G + (size_t)s0 * 40) + l);
            uint2 v1 = __ldg((const uint2*)(G + (size_t)s1 * 40) + l);
            __half2* p0 = (__half2*)&v0;
            __half2* p1 = (__half2*)&v1;
            float2 f;
            f = __half22float2(p0[0]); a0 += f.x; a1 += f.y;
            f = __half22float2(p0[1]); a2 += f.x; a3 += f.y;
            f = __half22float2(p1[0]); a0 += f.x; a1 += f.y;
            f = __half22float2(p1[1]); a2 += f.x; a3 += f.y;
        }
    }
    if (e < end) {
        int s0 = g_col[e];
        if ((unsigned)s0 >= (unsigned)n) s0 = 0;
        if (act) {
            uint2 v0 = __ldg((const uint2*)(G + (size_t)s0 * 40) + l);
            __half2* p0 = (__half2*)&v0;
            float2 f;
            f = __half22float2(p0[0]); a0 += f.x; a1 += f.y;
            f = __half22float2(p0[1]); a2 += f.x; a3 += f.y;
        }
    }

    if (act) {
        float4 o;
        o.x = fmaf(a0, di, g_bc[c]);
        o.y = fmaf(a1, di, g_bc[c + 1]);
        o.z = fmaf(a2, di, g_bc[c + 2]);
        o.w = fmaf(a3, di, g_bc[c + 3]);
        *(float4*)&OUT[(size_t)hw * 40 + c] = o;
    }
}

// ===========================================================================
extern "C" void kernel_launch(void* const* d_in, const int* in_sizes, int n_in,
                              void* d_out, int out_size)
{
    const float* x  = (const float*)d_in[0];
    const void*  ei = d_in[1];
    const float* W1 = (const float*)d_in[2];
    const float* b1 = (const float*)d_in[3];
    const float* W2 = (const float*)d_in[4];
    const float* b2 = (const float*)d_in[5];
    const float* W3 = (const float*)d_in[6];
    const float* b3 = (const float*)d_in[7];
    const float* Wl = (const float*)d_in[8];
    const float* bl = (const float*)d_in[9];
    float* out = (float*)d_out;

    int N = in_sizes[0] / FDIM;
    int E = in_sizes[1] / 2;
    if (N > NNODES) N = NNODES;
    if (E > NEDGES) E = NEDGES;

    __half *hp = nullptr, *gp = nullptr;
    float  *ap = nullptr;
    cudaGetSymbolAddress((void**)&hp, g_h);
    cudaGetSymbolAddress((void**)&ap, g_a);
    cudaGetSymbolAddress((void**)&gp, g_g3);

    // One-time stream/event infra (created on first, uncaptured, call)
    static cudaStream_t s2 = nullptr;
    static cudaEvent_t evFork, evCsr;
    if (!s2) {
        cudaStreamCreateWithFlags(&s2, cudaStreamNonBlocking);
        cudaEventCreateWithFlags(&evFork, cudaEventDisableTiming);
        cudaEventCreateWithFlags(&evCsr,  cudaEventDisableTiming);
    }

    int nb = (N + 255) / 256;
    int eb = (E + 255) / 256;
    int gemm_blocks = (N + 31) / 32;
    int agg_blocks  = (N * 16 + 255) / 256;   // 16 lanes per node

    // --- Serial prefix: deg + dis (needed by gemm1 epilogue) ---
    k_boot     <<<nb, 256>>>(N);
    k_detect   <<<1, 256>>>((const int*)ei, 2 * E);
    k_count_deg<<<eb, 256>>>(ei, E, N);
    k_dis      <<<nb, 256>>>(N);

    // --- Fork: CSR tail on s2, concurrent with gemm1 on main ---
    cudaEventRecord(evFork, 0);
    cudaStreamWaitEvent(s2, evFork, 0);
    k_scan_block<<<nb, 256, 0, s2>>>(N);
    k_scan_spine<<<1, 512, 0, s2>>>(nb);
    k_finalize  <<<nb, 256, 0, s2>>>(N, E);
    k_scatter   <<<eb, 256, 0, s2>>>(ei, E, N);
    k_fuseW     <<<1, 256, 0, s2>>>(W3, Wl, b3, bl);
    cudaEventRecord(evCsr, s2);

    k_gemm128<<<gemm_blocks, 128>>>(x, W1, hp, nullptr, 0, N);
    cudaStreamWaitEvent(0, evCsr, 0);    // join: agg needs CSR

    // --- Serial layer chain ---
    k_agg    <<<agg_blocks, 256>>>(hp, ap, N, E);
    k_gemm128<<<gemm_blocks, 128>>>(ap, W2, hp, b1, 1, N);
    k_agg    <<<agg_blocks, 256>>>(hp, ap, N, E);
    k_gemm3  <<<2048, 256>>>(ap, b2, gp, N);
    k_agg40  <<<agg_blocks, 256>>>(gp, out, N, E);
}

// round 13
// speedup vs baseline: 1.2891x; 1.0261x over previous
#include <cuda_runtime.h>
#include <cuda_fp16.h>
#include <cstdint>

#define NNODES 100000
#define NEDGES 1600000
#define FDIM   128

// Scratch (device globals — no allocation allowed anywhere)
__device__ __half g_h [(size_t)NNODES * FDIM]; // dis-scaled messages (fp16)
__device__ __half g_a [(size_t)NNODES * FDIM]; // aggregated features (fp16)
__device__ __half g_g3[(size_t)NNODES * 40];   // layer-3 fused messages (fp16)
__device__ float  g_dis[NNODES];               // (deg+1)^{-1/2}
__device__ int    g_deg[NNODES];
__device__ int    g_rowp[NNODES + 1];
__device__ int    g_cursor[NNODES];
__device__ int    g_col[NEDGES];
__device__ int    g_bsum[512];
__device__ int    g_boff[512];
__device__ int    g_is64;
__device__ float  g_Wc[128 * 40];              // W3 @ Wl
__device__ float  g_bc[40];                    // b3 @ Wl + bl

// ===========================================================================
// Boot: zero deg + dtype detection (prefix of 256 odd words; int64 small
// values have all odd int32 words zero — false negative prob ~0)
// ===========================================================================
__global__ void k_boot(const int* __restrict__ p, int twoE, int n) {
    int i = blockIdx.x * blockDim.x + threadIdx.x;
    if (i < n) g_deg[i] = 0;
    if (blockIdx.x == 0) {
        if (threadIdx.x == 0) g_is64 = 1;
        __syncthreads();
        int idx = 2 * threadIdx.x + 1;
        if (idx < twoE && p[idx] != 0) g_is64 = 0;
    }
}

__device__ __forceinline__ int load_edge(const void* ei, size_t idx, int is64) {
    if (is64) return (int)((const long long*)ei)[idx];
    return ((const int*)ei)[idx];
}

// ===========================================================================
// Weight fusion: Wc = W3 @ Wl, bc = b3 @ Wl + bl
// ===========================================================================
__global__ void __launch_bounds__(256) k_fuseW(const float* __restrict__ W3,
                                               const float* __restrict__ Wl,
                                               const float* __restrict__ b3,
                                               const float* __restrict__ bl)
{
    __shared__ float Wls[128 * 40];
    int tid = threadIdx.x;
    for (int i = tid; i < 128 * 40; i += 256) Wls[i] = Wl[i];
    __syncthreads();

    for (int o = tid; o < 128 * 40; o += 256) {
        int i = o / 40, n = o % 40;
        float s = 0.f;
        #pragma unroll 8
        for (int k = 0; k < 128; k++)
            s = fmaf(W3[(size_t)i * FDIM + k], Wls[k * 40 + n], s);
        g_Wc[o] = s;
    }
    if (tid < 40) {
        float s = bl[tid];
        #pragma unroll 8
        for (int k = 0; k < 128; k++)
            s = fmaf(b3[k], Wls[k * 40 + tid], s);
        g_bc[tid] = s;
    }
}

// ===========================================================================
// CSR build
// ===========================================================================
__global__ void k_count_deg(const void* __restrict__ ei, int E, int n) {
    int e = blockIdx.x * blockDim.x + threadIdx.x;
    if (e >= E) return;
    int is64 = g_is64;
    int d = load_edge(ei, (size_t)E + e, is64);
    if ((unsigned)d < (unsigned)n) atomicAdd(&g_deg[d], 1);
}

__global__ void k_dis(int n) {
    int i = blockIdx.x * blockDim.x + threadIdx.x;
    if (i < n) g_dis[i] = rsqrtf((float)(g_deg[i] + 1));
}

__global__ void __launch_bounds__(256) k_scan_block(int n) {
    __shared__ int s[256];
    int tid = threadIdx.x;
    int i = blockIdx.x * 256 + tid;
    int v = (i < n) ? g_deg[i] : 0;
    s[tid] = v;
    __syncthreads();
    for (int off = 1; off < 256; off <<= 1) {
        int t = (tid >= off) ? s[tid - off] : 0;
        __syncthreads();
        s[tid] += t;
        __syncthreads();
    }
    if (i < n) g_rowp[i] = s[tid] - v;
    if (tid == 255 && blockIdx.x < 512) g_bsum[blockIdx.x] = s[255];
}

__global__ void __launch_bounds__(512) k_scan_spine(int nb) {
    __shared__ int s[512];
    int tid = threadIdx.x;
    int v = (tid < nb) ? g_bsum[tid] : 0;
    s[tid] = v;
    __syncthreads();
    for (int off = 1; off < 512; off <<= 1) {
        int t = (tid >= off) ? s[tid - off] : 0;
        __syncthreads();
        s[tid] += t;
        __syncthreads();
    }
    g_boff[tid] = s[tid] - v;
}

__global__ void k_finalize(int n, int E) {
    int i = blockIdx.x * blockDim.x + threadIdx.x;
    if (i >= n) return;
    int r = g_rowp[i] + g_boff[(i >> 8) & 511];
    g_rowp[i] = r;
    g_cursor[i] = r;
    if (i == 0) g_rowp[n] = E;
}

__global__ void k_scatter(const void* __restrict__ ei, int E, int n) {
    int e = blockIdx.x * blockDim.x + threadIdx.x;
    if (e >= E) return;
    int is64 = g_is64;
    int s = load_edge(ei, (size_t)e, is64);
    int d = load_edge(ei, (size_t)E + e, is64);
    if ((unsigned)s >= (unsigned)n || (unsigned)d >= (unsigned)n) return;
    int pos = atomicAdd(&g_cursor[d], 1);
    if ((unsigned)pos < (unsigned)NEDGES) g_col[pos] = s;
}

// ===========================================================================
// GEMM (4-k inner): H'(fp16) = dis[row] * ( f(X + bias) @ W )
// X is fp32 (layer 1) or fp16 (layers 2+), selected by xhalf.
// ===========================================================================
__global__ void __launch_bounds__(128)
k_gemm128(const void* __restrict__ Xv, const float* __restrict__ W,
          __half* __restrict__ H, const float* __restrict__ bias_in,
          int relu_in, int M, int xhalf)
{
    __shared__ __align__(16) float Xs[32 * 128];

    int tid = threadIdx.x;
    int cg  = tid & 31;
    int rg  = tid >> 5;

    int t0 = blockIdx.x * 32;
    if (t0 >= M) return;

    #pragma unroll
    for (int i = 0; i < 8; i++) {
        int idx = (tid + i * 128) * 4;
        int row = t0 + (idx >> 7);
        int col = idx & 127;
        float4 v = make_float4(0.f, 0.f, 0.f, 0.f);
        if (row < M) {
            if (xhalf) {
                uint2 hv = *(const uint2*)((const __half*)Xv + (size_t)row * FDIM + col);
                __half2* p = (__half2*)&hv;
                float2 f0 = __half22float2(p[0]);
                float2 f1 = __half22float2(p[1]);
                v = make_float4(f0.x, f0.y, f1.x, f1.y);
            } else {
                v = *(const float4*)((const float*)Xv + (size_t)row * FDIM + col);
            }
        }
        if (bias_in) {
            v.x += bias_in[col];     v.y += bias_in[col + 1];
            v.z += bias_in[col + 2]; v.w += bias_in[col + 3];
        }
        if (relu_in) {
            v.x = fmaxf(v.x, 0.f); v.y = fmaxf(v.y, 0.f);
            v.z = fmaxf(v.z, 0.f); v.w = fmaxf(v.w, 0.f);
        }
        *(float4*)&Xs[idx] = v;
    }
    __syncthreads();

    float acc[8][4];
    #pragma unroll
    for (int r = 0; r < 8; r++)
        #pragma unroll
        for (int c = 0; c < 4; c++) acc[r][c] = 0.f;

    const float4* Wp = (const float4*)W + cg;

    #pragma unroll 4
    for (int k = 0; k < 128; k += 4) {
        float4 xk[8];
        #pragma unroll
        for (int r = 0; r < 8; r++)
            xk[r] = *(const float4*)&Xs[(rg * 8 + r) * 128 + k];

        float4 w0 = __ldg(Wp + (size_t)(k + 0) * 32);
        float4 w1 = __ldg(Wp + (size_t)(k + 1) * 32);
        float4 w2 = __ldg(Wp + (size_t)(k + 2) * 32);
        float4 w3 = __ldg(Wp + (size_t)(k + 3) * 32);

        #pragma unroll
        for (int r = 0; r < 8; r++) {
            acc[r][0] = fmaf(xk[r].x, w0.x, acc[r][0]);
            acc[r][1] = fmaf(xk[r].x, w0.y, acc[r][1]);
            acc[r][2] = fmaf(xk[r].x, w0.z, acc[r][2]);
            acc[r][3] = fmaf(xk[r].x, w0.w, acc[r][3]);

            acc[r][0] = fmaf(xk[r].y, w1.x, acc[r][0]);
            acc[r][1] = fmaf(xk[r].y, w1.y, acc[r][1]);
            acc[r][2] = fmaf(xk[r].y, w1.z, acc[r][2]);
            acc[r][3] = fmaf(xk[r].y, w1.w, acc[r][3]);

            acc[r][0] = fmaf(xk[r].z, w2.x, acc[r][0]);
            acc[r][1] = fmaf(xk[r].z, w2.y, acc[r][1]);
            acc[r][2] = fmaf(xk[r].z, w2.z, acc[r][2]);
            acc[r][3] = fmaf(xk[r].z, w2.w, acc[r][3]);

            acc[r][0] = fmaf(xk[r].w, w3.x, acc[r][0]);
            acc[r][1] = fmaf(xk[r].w, w3.y, acc[r][1]);
            acc[r][2] = fmaf(xk[r].w, w3.z, acc[r][2]);
            acc[r][3] = fmaf(xk[r].w, w3.w, acc[r][3]);
        }
    }

    #pragma unroll
    for (int r = 0; r < 8; r++) {
        int row = t0 + rg * 8 + r;
        if (row < M) {
            float ds = g_dis[row];
            union { __half2 h[2]; uint2 u; } cv;
            cv.h[0] = __floats2half2_rn(acc[r][0] * ds, acc[r][1] * ds);
            cv.h[1] = __floats2half2_rn(acc[r][2] * ds, acc[r][3] * ds);
            *(uint2*)&H[(size_t)row * FDIM + cg * 4] = cv.u;
        }
    }
}

// ===========================================================================
// Layer-3 fused GEMM: G'(fp16) = dis[r] * ( relu(X(fp16) + b2) @ Wc[128,40] )
// ===========================================================================
__global__ void __launch_bounds__(256)
k_gemm3(const __half* __restrict__ X, const float* __restrict__ bias_in,
        __half* __restrict__ G, int M)
{
    __shared__ float Ws[128 * 40];
    __shared__ float xs[8][128];

    int tid  = threadIdx.x;
    int lane = tid & 31;
    int w    = tid >> 5;

    for (int i = tid; i < 128 * 40; i += 256) Ws[i] = g_Wc[i];
    __syncthreads();

    int col2 = 32 + (lane & 7);
    int nwarps = gridDim.x * 8;

    for (int r = blockIdx.x * 8 + w; r < M; r += nwarps) {
        uint2 hv = __ldg((const uint2*)(X + (size_t)r * FDIM) + lane);
        __half2* p = (__half2*)&hv;
        float2 f0 = __half22float2(p[0]);
        float2 f1 = __half22float2(p[1]);
        int c = lane * 4;
        float4 v = make_float4(f0.x + bias_in[c],     f0.y + bias_in[c + 1],
                               f1.x + bias_in[c + 2], f1.y + bias_in[c + 3]);
        v.x = fmaxf(v.x, 0.f); v.y = fmaxf(v.y, 0.f);
        v.z = fmaxf(v.z, 0.f); v.w = fmaxf(v.w, 0.f);
        *(float4*)&xs[w][lane * 4] = v;
        __syncwarp();

        float acc0 = 0.f, acc1 = 0.f;
        #pragma unroll 8
        for (int k = 0; k < 128; k++) {
            float xv = xs[w][k];
            acc0 = fmaf(xv, Ws[k * 40 + lane], acc0);
            acc1 = fmaf(xv, Ws[k * 40 + col2], acc1);
        }
        float ds = g_dis[r];
        G[(size_t)r * 40 + lane] = __float2half_rn(acc0 * ds);
        if (lane < 8)
            G[(size_t)r * 40 + 32 + lane] = __float2half_rn(acc1 * ds);
        __syncwarp();
    }
}

// ===========================================================================
// Aggregation (fp16 gather, fp16 out): 16 lanes per dst node, fp32 accumulate.
// ===========================================================================
__device__ __forceinline__ void acc_h8(float* a, uint4 v) {
    __half2* p = (__half2*)&v;
    float2 f0 = __half22float2(p[0]);
    float2 f1 = __half22float2(p[1]);
    float2 f2 = __half22float2(p[2]);
    float2 f3 = __half22float2(p[3]);
    a[0] += f0.x; a[1] += f0.y; a[2] += f1.x; a[3] += f1.y;
    a[4] += f2.x; a[5] += f2.y; a[6] += f3.x; a[7] += f3.y;
}

__global__ void __launch_bounds__(256)
k_agg(const __half* __restrict__ H, __half* __restrict__ A, int n, int E)
{
    int node = (blockIdx.x * blockDim.x + threadIdx.x) >> 4;
    int hl   = threadIdx.x & 15;
    if (node >= n) return;

    float di = g_dis[node];
    int beg = g_rowp[node];
    int end = g_rowp[node + 1];
    if (beg < 0) beg = 0;
    if (end > E) end = E;

    float a[8];
    {
        uint4 sv = __ldg((const uint4*)(H + (size_t)node * FDIM) + hl);
        __half2* p = (__half2*)&sv;
        float2 f0 = __half22float2(p[0]);
        float2 f1 = __half22float2(p[1]);
        float2 f2 = __half22float2(p[2]);
        float2 f3 = __half22float2(p[3]);
        a[0] = f0.x; a[1] = f0.y; a[2] = f1.x; a[3] = f1.y;
        a[4] = f2.x; a[5] = f2.y; a[6] = f3.x; a[7] = f3.y;
    }

    int e = beg;
    for (; e + 2 <= end; e += 2) {
        int s0 = g_col[e];
        int s1 = g_col[e + 1];
        if ((unsigned)s0 >= (unsigned)n) s0 = 0;
        if ((unsigned)s1 >= (unsigned)n) s1 = 0;
        uint4 v0 = __ldg((const uint4*)(H + (size_t)s0 * FDIM) + hl);
        uint4 v1 = __ldg((const uint4*)(H + (size_t)s1 * FDIM) + hl);
        acc_h8(a, v0);
        acc_h8(a, v1);
    }
    if (e < end) {
        int s0 = g_col[e];
        if ((unsigned)s0 >= (unsigned)n) s0 = 0;
        uint4 v0 = __ldg((const uint4*)(H + (size_t)s0 * FDIM) + hl);
        acc_h8(a, v0);
    }

    union { __half2 h[4]; uint4 u; } cv;
    cv.h[0] = __floats2half2_rn(a[0] * di, a[1] * di);
    cv.h[1] = __floats2half2_rn(a[2] * di, a[3] * di);
    cv.h[2] = __floats2half2_rn(a[4] * di, a[5] * di);
    cv.h[3] = __floats2half2_rn(a[6] * di, a[7] * di);
    *((uint4*)(A + (size_t)node * FDIM) + hl) = cv.u;
}

// ===========================================================================
// Layer-3 aggregation (fp16, 40-wide): OUT = dis[d]*(G'[d] + sum G'[s]) + bc
// ===========================================================================
__global__ void __launch_bounds__(256)
k_agg40(const __half* __restrict__ G, float* __restrict__ OUT, int n, int E)
{
    int hw = (blockIdx.x * blockDim.x + threadIdx.x) >> 4;
    int l  = threadIdx.x & 15;
    if (hw >= n) return;
    bool act = l < 10;
    int  c   = l * 4;

    float di = g_dis[hw];
    int beg = g_rowp[hw];
    int end = g_rowp[hw + 1];
    if (beg < 0) beg = 0;
    if (end > E) end = E;

    float a0 = 0.f, a1 = 0.f, a2 = 0.f, a3 = 0.f;
    if (act) {
        uint2 sv = __ldg((const uint2*)(G + (size_t)hw * 40) + l);
        __half2* p = (__half2*)&sv;
        float2 f0 = __half22float2(p[0]);
        float2 f1 = __half22float2(p[1]);
        a0 = f0.x; a1 = f0.y; a2 = f1.x; a3 = f1.y;
    }

    int e = beg;
    for (; e + 2 <= end; e += 2) {
        int s0 = g_col[e];
        int s1 = g_col[e + 1];
        if ((unsigned)s0 >= (unsigned)n) s0 = 0;
        if ((unsigned)s1 >= (unsigned)n) s1 = 0;
        if (act) {
            uint2 v0 = __ldg((const uint2*)(G + (size_t)s0 * 40) + l);
            uint2 v1 = __ldg((const uint2*)(G + (size_t)s1 * 40) + l);
            __half2* p0 = (__half2*)&v0;
            __half2* p1 = (__half2*)&v1;
            float2 f;
            f = __half22float2(p0[0]); a0 += f.x; a1 += f.y;
            f = __half22float2(p0[1]); a2 += f.x; a3 += f.y;
            f = __half22float2(p1[0]); a0 += f.x; a1 += f.y;
            f = __half22float2(p1[1]); a2 += f.x; a3 += f.y;
        }
    }
    if (e < end) {
        int s0 = g_col[e];
        if ((unsigned)s0 >= (unsigned)n) s0 = 0;
        if (act) {
            uint2 v0 = __ldg((const uint2*)(G + (size_t)s0 * 40) + l);
            __half2* p0 = (__half2*)&v0;
            float2 f;
            f = __half22float2(p0[0]); a0 += f.x; a1 += f.y;
            f = __half22float2(p0[1]); a2 += f.x; a3 += f.y;
        }
    }

    if (act) {
        float4 o;
        o.x = fmaf(a0, di, g_bc[c]);
        o.y = fmaf(a1, di, g_bc[c + 1]);
        o.z = fmaf(a2, di, g_bc[c + 2]);
        o.w = fmaf(a3, di, g_bc[c + 3]);
        *(float4*)&OUT[(size_t)hw * 40 + c] = o;
    }
}

// ===========================================================================
extern "C" void kernel_launch(void* const* d_in, const int* in_sizes, int n_in,
                              void* d_out, int out_size)
{
    const float* x  = (const float*)d_in[0];
    const void*  ei = d_in[1];
    const float* W1 = (const float*)d_in[2];
    const float* b1 = (const float*)d_in[3];
    const float* W2 = (const float*)d_in[4];
    const float* b2 = (const float*)d_in[5];
    const float* W3 = (const float*)d_in[6];
    const float* b3 = (const float*)d_in[7];
    const float* Wl = (const float*)d_in[8];
    const float* bl = (const float*)d_in[9];
    float* out = (float*)d_out;

    int N = in_sizes[0] / FDIM;
    int E = in_sizes[1] / 2;
    if (N > NNODES) N = NNODES;
    if (E > NEDGES) E = NEDGES;

    __half *hp = nullptr, *ap = nullptr, *gp = nullptr;
    cudaGetSymbolAddress((void**)&hp, g_h);
    cudaGetSymbolAddress((void**)&ap, g_a);
    cudaGetSymbolAddress((void**)&gp, g_g3);

    // One-time stream/event infra (created on first, uncaptured, call)
    static cudaStream_t s2 = nullptr;
    static cudaEvent_t evFork, evCsr;
    if (!s2) {
        cudaStreamCreateWithFlags(&s2, cudaStreamNonBlocking);
        cudaEventCreateWithFlags(&evFork, cudaEventDisableTiming);
        cudaEventCreateWithFlags(&evCsr,  cudaEventDisableTiming);
    }

    int nb = (N + 255) / 256;
    int eb = (E + 255) / 256;
    int gemm_blocks = (N + 31) / 32;
    int agg_blocks  = (N * 16 + 255) / 256;   // 16 lanes per node

    // --- Serial prefix: deg + dis (needed by gemm1 epilogue) ---
    k_boot     <<<nb, 256>>>((const int*)ei, 2 * E, N);
    k_count_deg<<<eb, 256>>>(ei, E, N);
    k_dis      <<<nb, 256>>>(N);

    // --- Fork: CSR tail on s2, concurrent with gemm1 on main ---
    cudaEventRecord(evFork, 0);
    cudaStreamWaitEvent(s2, evFork, 0);
    k_scan_block<<<nb, 256, 0, s2>>>(N);
    k_scan_spine<<<1, 512, 0, s2>>>(nb);
    k_finalize  <<<nb, 256, 0, s2>>>(N, E);
    k_scatter   <<<eb, 256, 0, s2>>>(ei, E, N);
    k_fuseW     <<<1, 256, 0, s2>>>(W3, Wl, b3, bl);
    cudaEventRecord(evCsr, s2);

    k_gemm128<<<gemm_blocks, 128>>>(x, W1, hp, nullptr, 0, N, 0);
    cudaStreamWaitEvent(0, evCsr, 0);    // join: agg needs CSR

    // --- Serial layer chain ---
    k_agg    <<<agg_blocks, 256>>>(hp, ap, N, E);
    k_gemm128<<<gemm_blocks, 128>>>(ap, W2, hp, b1, 1, N, 1);
    k_agg    <<<agg_blocks, 256>>>(hp, ap, N, E);
    k_gemm3  <<<2048, 256>>>(ap, b2, gp, N);
    k_agg40  <<<agg_blocks, 256>>>(gp, out, N, E);
}

// round 14
// speedup vs baseline: 1.2975x; 1.0065x over previous
#include <cuda_runtime.h>
#include <cuda_fp16.h>
#include <cstdint>

#define NNODES 100000
#define NEDGES 1600000
#define FDIM   128

// Scratch (device globals — no allocation allowed anywhere)
__device__ __half g_h [(size_t)NNODES * FDIM]; // layer-1 messages (fp16)
__device__ __half g_h2[(size_t)NNODES * FDIM]; // layer-2 messages (fp16)
__device__ __half g_g3[(size_t)NNODES * 40];   // layer-3 fused messages (fp16)
__device__ float  g_dis[NNODES];               // (deg+1)^{-1/2}
__device__ int    g_deg[NNODES];
__device__ int    g_rowp[NNODES + 1];
__device__ int    g_cursor[NNODES];
__device__ int    g_col[NEDGES];
__device__ int    g_bsum[512];
__device__ int    g_boff[512];
__device__ int    g_is64;
__device__ float  g_Wc[128 * 40];              // W3 @ Wl
__device__ float  g_bc[40];                    // b3 @ Wl + bl

// ===========================================================================
// Boot: zero deg + dtype detection (256-odd-word prefix)
// ===========================================================================
__global__ void k_boot(const int* __restrict__ p, int twoE, int n) {
    int i = blockIdx.x * blockDim.x + threadIdx.x;
    if (i < n) g_deg[i] = 0;
    if (blockIdx.x == 0) {
        if (threadIdx.x == 0) g_is64 = 1;
        __syncthreads();
        int idx = 2 * threadIdx.x + 1;
        if (idx < twoE && p[idx] != 0) g_is64 = 0;
    }
}

__device__ __forceinline__ int load_edge(const void* ei, size_t idx, int is64) {
    if (is64) return (int)((const long long*)ei)[idx];
    return ((const int*)ei)[idx];
}

// ===========================================================================
// Weight fusion: Wc = W3 @ Wl, bc = b3 @ Wl + bl
// ===========================================================================
__global__ void __launch_bounds__(256) k_fuseW(const float* __restrict__ W3,
                                               const float* __restrict__ Wl,
                                               const float* __restrict__ b3,
                                               const float* __restrict__ bl)
{
    __shared__ float Wls[128 * 40];
    int tid = threadIdx.x;
    for (int i = tid; i < 128 * 40; i += 256) Wls[i] = Wl[i];
    __syncthreads();

    for (int o = tid; o < 128 * 40; o += 256) {
        int i = o / 40, n = o % 40;
        float s = 0.f;
        #pragma unroll 8
        for (int k = 0; k < 128; k++)
            s = fmaf(W3[(size_t)i * FDIM + k], Wls[k * 40 + n], s);
        g_Wc[o] = s;
    }
    if (tid < 40) {
        float s = bl[tid];
        #pragma unroll 8
        for (int k = 0; k < 128; k++)
            s = fmaf(b3[k], Wls[k * 40 + tid], s);
        g_bc[tid] = s;
    }
}

// ===========================================================================
// CSR build
// ===========================================================================
__global__ void k_count_deg(const void* __restrict__ ei, int E, int n) {
    int e = blockIdx.x * blockDim.x + threadIdx.x;
    if (e >= E) return;
    int is64 = g_is64;
    int d = load_edge(ei, (size_t)E + e, is64);
    if ((unsigned)d < (unsigned)n) atomicAdd(&g_deg[d], 1);
}

__global__ void k_dis(int n) {
    int i = blockIdx.x * blockDim.x + threadIdx.x;
    if (i < n) g_dis[i] = rsqrtf((float)(g_deg[i] + 1));
}

__global__ void __launch_bounds__(256) k_scan_block(int n) {
    __shared__ int s[256];
    int tid = threadIdx.x;
    int i = blockIdx.x * 256 + tid;
    int v = (i < n) ? g_deg[i] : 0;
    s[tid] = v;
    __syncthreads();
    for (int off = 1; off < 256; off <<= 1) {
        int t = (tid >= off) ? s[tid - off] : 0;
        __syncthreads();
        s[tid] += t;
        __syncthreads();
    }
    if (i < n) g_rowp[i] = s[tid] - v;
    if (tid == 255 && blockIdx.x < 512) g_bsum[blockIdx.x] = s[255];
}

__global__ void __launch_bounds__(512) k_scan_spine(int nb) {
    __shared__ int s[512];
    int tid = threadIdx.x;
    int v = (tid < nb) ? g_bsum[tid] : 0;
    s[tid] = v;
    __syncthreads();
    for (int off = 1; off < 512; off <<= 1) {
        int t = (tid >= off) ? s[tid - off] : 0;
        __syncthreads();
        s[tid] += t;
        __syncthreads();
    }
    g_boff[tid] = s[tid] - v;
}

__global__ void k_finalize(int n, int E) {
    int i = blockIdx.x * blockDim.x + threadIdx.x;
    if (i >= n) return;
    int r = g_rowp[i] + g_boff[(i >> 8) & 511];
    g_rowp[i] = r;
    g_cursor[i] = r;
    if (i == 0) g_rowp[n] = E;
}

__global__ void k_scatter(const void* __restrict__ ei, int E, int n) {
    int e = blockIdx.x * blockDim.x + threadIdx.x;
    if (e >= E) return;
    int is64 = g_is64;
    int s = load_edge(ei, (size_t)e, is64);
    int d = load_edge(ei, (size_t)E + e, is64);
    if ((unsigned)s >= (unsigned)n || (unsigned)d >= (unsigned)n) return;
    int pos = atomicAdd(&g_cursor[d], 1);
    if ((unsigned)pos < (unsigned)NEDGES) g_col[pos] = s;
}

// ===========================================================================
// Shared agg helper: half-warp aggregates one node's fp16 row into fp32 a[8].
// ===========================================================================
__device__ __forceinline__ void acc_h8(float* a, uint4 v) {
    __half2* p = (__half2*)&v;
    float2 f0 = __half22float2(p[0]);
    float2 f1 = __half22float2(p[1]);
    float2 f2 = __half22float2(p[2]);
    float2 f3 = __half22float2(p[3]);
    a[0] += f0.x; a[1] += f0.y; a[2] += f1.x; a[3] += f1.y;
    a[4] += f2.x; a[5] += f2.y; a[6] += f3.x; a[7] += f3.y;
}

__device__ __forceinline__ void agg_node(const __half* __restrict__ H,
                                         int node, int hl, int n, int E,
                                         float* a)
{
    int beg = g_rowp[node];
    int end = g_rowp[node + 1];
    if (beg < 0) beg = 0;
    if (end > E) end = E;

    uint4 sv = __ldg((const uint4*)(H + (size_t)node * FDIM) + hl);
    {
        __half2* p = (__half2*)&sv;
        float2 f0 = __half22float2(p[0]);
        float2 f1 = __half22float2(p[1]);
        float2 f2 = __half22float2(p[2]);
        float2 f3 = __half22float2(p[3]);
        a[0] = f0.x; a[1] = f0.y; a[2] = f1.x; a[3] = f1.y;
        a[4] = f2.x; a[5] = f2.y; a[6] = f3.x; a[7] = f3.y;
    }

    int e = beg;
    for (; e + 2 <= end; e += 2) {
        int s0 = g_col[e];
        int s1 = g_col[e + 1];
        if ((unsigned)s0 >= (unsigned)n) s0 = 0;
        if ((unsigned)s1 >= (unsigned)n) s1 = 0;
        uint4 v0 = __ldg((const uint4*)(H + (size_t)s0 * FDIM) + hl);
        uint4 v1 = __ldg((const uint4*)(H + (size_t)s1 * FDIM) + hl);
        acc_h8(a, v0);
        acc_h8(a, v1);
    }
    if (e < end) {
        int s0 = g_col[e];
        if ((unsigned)s0 >= (unsigned)n) s0 = 0;
        uint4 v0 = __ldg((const uint4*)(H + (size_t)s0 * FDIM) + hl);
        acc_h8(a, v0);
    }
}

// ===========================================================================
// GEMM layer 1 (4-k inner): H'(fp16) = dis[row] * ( X(fp32) @ W )
// ===========================================================================
__global__ void __launch_bounds__(128)
k_gemm1(const float* __restrict__ X, const float* __restrict__ W,
        __half* __restrict__ H, int M)
{
    __shared__ __align__(16) float Xs[32 * 128];

    int tid = threadIdx.x;
    int cg  = tid & 31;
    int rg  = tid >> 5;

    int t0 = blockIdx.x * 32;
    if (t0 >= M) return;

    #pragma unroll
    for (int i = 0; i < 8; i++) {
        int idx = (tid + i * 128) * 4;
        int row = t0 + (idx >> 7);
        float4 v = make_float4(0.f, 0.f, 0.f, 0.f);
        if (row < M) v = *(const float4*)&X[(size_t)row * FDIM + (idx & 127)];
        *(float4*)&Xs[idx] = v;
    }
    __syncthreads();

    float acc[8][4];
    #pragma unroll
    for (int r = 0; r < 8; r++)
        #pragma unroll
        for (int c = 0; c < 4; c++) acc[r][c] = 0.f;

    const float4* Wp = (const float4*)W + cg;

    #pragma unroll 4
    for (int k = 0; k < 128; k += 4) {
        float4 xk[8];
        #pragma unroll
        for (int r = 0; r < 8; r++)
            xk[r] = *(const float4*)&Xs[(rg * 8 + r) * 128 + k];

        float4 w0 = __ldg(Wp + (size_t)(k + 0) * 32);
        float4 w1 = __ldg(Wp + (size_t)(k + 1) * 32);
        float4 w2 = __ldg(Wp + (size_t)(k + 2) * 32);
        float4 w3 = __ldg(Wp + (size_t)(k + 3) * 32);

        #pragma unroll
        for (int r = 0; r < 8; r++) {
            acc[r][0] = fmaf(xk[r].x, w0.x, acc[r][0]);
            acc[r][1] = fmaf(xk[r].x, w0.y, acc[r][1]);
            acc[r][2] = fmaf(xk[r].x, w0.z, acc[r][2]);
            acc[r][3] = fmaf(xk[r].x, w0.w, acc[r][3]);

            acc[r][0] = fmaf(xk[r].y, w1.x, acc[r][0]);
            acc[r][1] = fmaf(xk[r].y, w1.y, acc[r][1]);
            acc[r][2] = fmaf(xk[r].y, w1.z, acc[r][2]);
            acc[r][3] = fmaf(xk[r].y, w1.w, acc[r][3]);

            acc[r][0] = fmaf(xk[r].z, w2.x, acc[r][0]);
            acc[r][1] = fmaf(xk[r].z, w2.y, acc[r][1]);
            acc[r][2] = fmaf(xk[r].z, w2.z, acc[r][2]);
            acc[r][3] = fmaf(xk[r].z, w2.w, acc[r][3]);

            acc[r][0] = fmaf(xk[r].w, w3.x, acc[r][0]);
            acc[r][1] = fmaf(xk[r].w, w3.y, acc[r][1]);
            acc[r][2] = fmaf(xk[r].w, w3.z, acc[r][2]);
            acc[r][3] = fmaf(xk[r].w, w3.w, acc[r][3]);
        }
    }

    #pragma unroll
    for (int r = 0; r < 8; r++) {
        int row = t0 + rg * 8 + r;
        if (row < M) {
            float ds = g_dis[row];
            union { __half2 h[2]; uint2 u; } cv;
            cv.h[0] = __floats2half2_rn(acc[r][0] * ds, acc[r][1] * ds);
            cv.h[1] = __floats2half2_rn(acc[r][2] * ds, acc[r][3] * ds);
            *(uint2*)&H[(size_t)row * FDIM + cg * 4] = cv.u;
        }
    }
}

// ===========================================================================
// FUSED agg + GEMM128 (layer 2):
//   phase 1: Xs[32][128] = relu( dis*(Hin[d] + sum Hin[s]) + bias )   (fp32)
//   phase 2: Hout(fp16) = dis[row] * ( Xs @ W )
// ===========================================================================
__global__ void __launch_bounds__(128)
k_fused2(const __half* __restrict__ Hin, const float* __restrict__ W,
         __half* __restrict__ Hout, const float* __restrict__ bias,
         int n, int E)
{
    __shared__ __align__(16) float Xs[32 * 128];

    int tid = threadIdx.x;
    int t0 = blockIdx.x * 32;

    // --- phase 1: aggregate 32 nodes; 8 half-warps -> 4 passes ---
    {
        int hwid = tid >> 4;   // 0..7
        int hl   = tid & 15;
        float b[8];
        #pragma unroll
        for (int i = 0; i < 8; i++) b[i] = bias[hl * 8 + i];

        #pragma unroll
        for (int pass = 0; pass < 4; pass++) {
            int local = pass * 8 + hwid;
            int node = t0 + local;
            float a[8] = {0, 0, 0, 0, 0, 0, 0, 0};
            float di = 0.f;
            if (node < n) {
                di = g_dis[node];
                agg_node(Hin, node, hl, n, E, a);
            }
            #pragma unroll
            for (int i = 0; i < 8; i++)
                Xs[local * 128 + hl * 8 + i] = fmaxf(fmaf(a[i], di, b[i]), 0.f);
        }
    }
    __syncthreads();

    // --- phase 2: GEMM from smem tile ---
    int cg = tid & 31;
    int rg = tid >> 5;

    float acc[8][4];
    #pragma unroll
    for (int r = 0; r < 8; r++)
        #pragma unroll
        for (int c = 0; c < 4; c++) acc[r][c] = 0.f;

    const float4* Wp = (const float4*)W + cg;

    #pragma unroll 4
    for (int k = 0; k < 128; k += 4) {
        float4 xk[8];
        #pragma unroll
        for (int r = 0; r < 8; r++)
            xk[r] = *(const float4*)&Xs[(rg * 8 + r) * 128 + k];

        float4 w0 = __ldg(Wp + (size_t)(k + 0) * 32);
        float4 w1 = __ldg(Wp + (size_t)(k + 1) * 32);
        float4 w2 = __ldg(Wp + (size_t)(k + 2) * 32);
        float4 w3 = __ldg(Wp + (size_t)(k + 3) * 32);

        #pragma unroll
        for (int r = 0; r < 8; r++) {
            acc[r][0] = fmaf(xk[r].x, w0.x, acc[r][0]);
            acc[r][1] = fmaf(xk[r].x, w0.y, acc[r][1]);
            acc[r][2] = fmaf(xk[r].x, w0.z, acc[r][2]);
            acc[r][3] = fmaf(xk[r].x, w0.w, acc[r][3]);

            acc[r][0] = fmaf(xk[r].y, w1.x, acc[r][0]);
            acc[r][1] = fmaf(xk[r].y, w1.y, acc[r][1]);
            acc[r][2] = fmaf(xk[r].y, w1.z, acc[r][2]);
            acc[r][3] = fmaf(xk[r].y, w1.w, acc[r][3]);

            acc[r][0] = fmaf(xk[r].z, w2.x, acc[r][0]);
            acc[r][1] = fmaf(xk[r].z, w2.y, acc[r][1]);
            acc[r][2] = fmaf(xk[r].z, w2.z, acc[r][2]);
            acc[r][3] = fmaf(xk[r].z, w2.w, acc[r][3]);

            acc[r][0] = fmaf(xk[r].w, w3.x, acc[r][0]);
            acc[r][1] = fmaf(xk[r].w, w3.y, acc[r][1]);
            acc[r][2] = fmaf(xk[r].w, w3.z, acc[r][2]);
            acc[r][3] = fmaf(xk[r].w, w3.w, acc[r][3]);
        }
    }

    #pragma unroll
    for (int r = 0; r < 8; r++) {
        int row = t0 + rg * 8 + r;
        if (row < n) {
            float ds = g_dis[row];
            union { __half2 h[2]; uint2 u; } cv;
            cv.h[0] = __floats2half2_rn(acc[r][0] * ds, acc[r][1] * ds);
            cv.h[1] = __floats2half2_rn(acc[r][2] * ds, acc[r][3] * ds);
            *(uint2*)&Hout[(size_t)row * FDIM + cg * 4] = cv.u;
        }
    }
}

// ===========================================================================
// FUSED agg + GEMM3 (layer 3): agg -> Xs, then Xs @ Wc (128x40) -> G (fp16)
// ===========================================================================
__global__ void __launch_bounds__(128)
k_fused3(const __half* __restrict__ Hin, __half* __restrict__ G,
         const float* __restrict__ bias, int n, int E)
{
    __shared__ __align__(16) float Xs[32 * 128];   // 16 KB
    __shared__ float Ws[128 * 40];                 // 20 KB

    int tid = threadIdx.x;
    int t0 = blockIdx.x * 32;

    for (int i = tid; i < 128 * 40; i += 128) Ws[i] = g_Wc[i];

    // --- phase 1: aggregate 32 nodes ---
    {
        int hwid = tid >> 4;
        int hl   = tid & 15;
        float b[8];
        #pragma unroll
        for (int i = 0; i < 8; i++) b[i] = bias[hl * 8 + i];

        #pragma unroll
        for (int pass = 0; pass < 4; pass++) {
            int local = pass * 8 + hwid;
            int node = t0 + local;
            float a[8] = {0, 0, 0, 0, 0, 0, 0, 0};
            float di = 0.f;
            if (node < n) {
                di = g_dis[node];
                agg_node(Hin, node, hl, n, E, a);
            }
            #pragma unroll
            for (int i = 0; i < 8; i++)
                Xs[local * 128 + hl * 8 + i] = fmaxf(fmaf(a[i], di, b[i]), 0.f);
        }
    }
    __syncthreads();

    // --- phase 2: 4 warps x 8 rows, 40 output cols per row ---
    int lane = tid & 31;
    int w    = tid >> 5;
    int col2 = 32 + (lane & 7);

    #pragma unroll
    for (int rr = 0; rr < 8; rr++) {
        int local = w * 8 + rr;
        int row = t0 + local;
        float acc0 = 0.f, acc1 = 0.f;
        #pragma unroll 8
        for (int k = 0; k < 128; k++) {
            float xv = Xs[local * 128 + k];
            acc0 = fmaf(xv, Ws[k * 40 + lane], acc0);
            acc1 = fmaf(xv, Ws[k * 40 + col2], acc1);
        }
        if (row < n) {
            float ds = g_dis[row];
            G[(size_t)row * 40 + lane] = __float2half_rn(acc0 * ds);
            if (lane < 8)
                G[(size_t)row * 40 + 32 + lane] = __float2half_rn(acc1 * ds);
        }
    }
}

// ===========================================================================
// Layer-3 aggregation (fp16, 40-wide): OUT = dis[d]*(G'[d] + sum G'[s]) + bc
// ===========================================================================
__global__ void __launch_bounds__(256)
k_agg40(const __half* __restrict__ G, float* __restrict__ OUT, int n, int E)
{
    int hw = (blockIdx.x * blockDim.x + threadIdx.x) >> 4;
    int l  = threadIdx.x & 15;
    if (hw >= n) return;
    bool act = l < 10;
    int  c   = l * 4;

    float di = g_dis[hw];
    int beg = g_rowp[hw];
    int end = g_rowp[hw + 1];
    if (beg < 0) beg = 0;
    if (end > E) end = E;

    float a0 = 0.f, a1 = 0.f, a2 = 0.f, a3 = 0.f;
    if (act) {
        uint2 sv = __ldg((const uint2*)(G + (size_t)hw * 40) + l);
        __half2* p = (__half2*)&sv;
        float2 f0 = __half22float2(p[0]);
        float2 f1 = __half22float2(p[1]);
        a0 = f0.x; a1 = f0.y; a2 = f1.x; a3 = f1.y;
    }

    int e = beg;
    for (; e + 2 <= end; e += 2) {
        int s0 = g_col[e];
        int s1 = g_col[e + 1];
        if ((unsigned)s0 >= (unsigned)n) s0 = 0;
        if ((unsigned)s1 >= (unsigned)n) s1 = 0;
        if (act) {
            uint2 v0 = __ldg((const uint2*)(G + (size_t)s0 * 40) + l);
            uint2 v1 = __ldg((const uint2*)(G + (size_t)s1 * 40) + l);
            __half2* p0 = (__half2*)&v0;
            __half2* p1 = (__half2*)&v1;
            float2 f;
            f = __half22float2(p0[0]); a0 += f.x; a1 += f.y;
            f = __half22float2(p0[1]); a2 += f.x; a3 += f.y;
            f = __half22float2(p1[0]); a0 += f.x; a1 += f.y;
            f = __half22float2(p1[1]); a2 += f.x; a3 += f.y;
        }
    }
    if (e < end) {
        int s0 = g_col[e];
        if ((unsigned)s0 >= (unsigned)n) s0 = 0;
        if (act) {
            uint2 v0 = __ldg((const uint2*)(G + (size_t)s0 * 40) + l);
            __half2* p0 = (__half2*)&v0;
            float2 f;
            f = __half22float2(p0[0]); a0 += f.x; a1 += f.y;
            f = __half22float2(p0[1]); a2 += f.x; a3 += f.y;
        }
    }

    if (act) {
        float4 o;
        o.x = fmaf(a0, di, g_bc[c]);
        o.y = fmaf(a1, di, g_bc[c + 1]);
        o.z = fmaf(a2, di, g_bc[c + 2]);
        o.w = fmaf(a3, di, g_bc[c + 3]);
        *(float4*)&OUT[(size_t)hw * 40 + c] = o;
    }
}

// ===========================================================================
extern "C" void kernel_launch(void* const* d_in, const int* in_sizes, int n_in,
                              void* d_out, int out_size)
{
    const float* x  = (const float*)d_in[0];
    const void*  ei = d_in[1];
    const float* W1 = (const float*)d_in[2];
    const float* b1 = (const float*)d_in[3];
    const float* W2 = (const float*)d_in[4];
    const float* b2 = (const float*)d_in[5];
    const float* W3 = (const float*)d_in[6];
    const float* b3 = (const float*)d_in[7];
    const float* Wl = (const float*)d_in[8];
    const float* bl = (const float*)d_in[9];
    float* out = (float*)d_out;

    int N = in_sizes[0] / FDIM;
    int E = in_sizes[1] / 2;
    if (N > NNODES) N = NNODES;
    if (E > NEDGES) E = NEDGES;

    __half *hp = nullptr, *h2p = nullptr, *gp = nullptr;
    cudaGetSymbolAddress((void**)&hp,  g_h);
    cudaGetSymbolAddress((void**)&h2p, g_h2);
    cudaGetSymbolAddress((void**)&gp,  g_g3);

    // One-time stream/event infra (created on first, uncaptured, call)
    static cudaStream_t s2 = nullptr;
    static cudaEvent_t evFork, evCsr;
    if (!s2) {
        cudaStreamCreateWithFlags(&s2, cudaStreamNonBlocking);
        cudaEventCreateWithFlags(&evFork, cudaEventDisableTiming);
        cudaEventCreateWithFlags(&evCsr,  cudaEventDisableTiming);
    }

    int nb = (N + 255) / 256;
    int eb = (E + 255) / 256;
    int tile_blocks = (N + 31) / 32;
    int agg40_blocks = (N * 16 + 255) / 256;

    // --- Serial prefix: deg + dis (needed by gemm1 epilogue) ---
    k_boot     <<<nb, 256>>>((const int*)ei, 2 * E, N);
    k_count_deg<<<eb, 256>>>(ei, E, N);
    k_dis      <<<nb, 256>>>(N);

    // --- Fork: CSR tail on s2, concurrent with gemm1 on main ---
    cudaEventRecord(evFork, 0);
    cudaStreamWaitEvent(s2, evFork, 0);
    k_scan_block<<<nb, 256, 0, s2>>>(N);
    k_scan_spine<<<1, 512, 0, s2>>>(nb);
    k_finalize  <<<nb, 256, 0, s2>>>(N, E);
    k_scatter   <<<eb, 256, 0, s2>>>(ei, E, N);
    k_fuseW     <<<1, 256, 0, s2>>>(W3, Wl, b3, bl);
    cudaEventRecord(evCsr, s2);

    k_gemm1<<<tile_blocks, 128>>>(x, W1, hp, N);
    cudaStreamWaitEvent(0, evCsr, 0);    // join: fused kernels need CSR

    // --- Fused layer chain ---
    k_fused2<<<tile_blocks, 128>>>(hp, W2, h2p, b1, N, E);
    k_fused3<<<tile_blocks, 128>>>(h2p, gp, b2, N, E);
    k_agg40 <<<agg40_blocks, 256>>>(gp, out, N, E);
}

// round 15
// speedup vs baseline: 2.1800x; 1.6802x over previous
#include <cuda_runtime.h>
#include <cuda_fp16.h>
#include <cstdint>

#define NNODES 100000
#define NEDGES 1600000
#define FDIM   128
#define SA     136            // padded smem A stride (halfs): 272 B, conflict-free

// Scratch (device globals — no allocation allowed anywhere)
__device__ __half g_h [(size_t)NNODES * FDIM]; // layer-1 messages (fp16)
__device__ __half g_h2[(size_t)NNODES * FDIM]; // layer-2 messages (fp16)
__device__ __half g_g3[(size_t)NNODES * 40];   // layer-3 fused messages (fp16)
__device__ float  g_dis[NNODES];               // (deg+1)^{-1/2}
__device__ int    g_deg[NNODES];
__device__ int    g_rowp[NNODES + 1];
__device__ int    g_cursor[NNODES];
__device__ int    g_col[NEDGES];
__device__ int    g_bsum[512];
__device__ int    g_boff[512];
__device__ int    g_is64;
__device__ float  g_Wc[128 * 40];              // W3 @ Wl (fp32)
__device__ float  g_bc[40];                    // b3 @ Wl + bl
// mma-fragment-ordered weights: [s(8)][j(J)][lane(32)] x uint2 {b0,b1}
__device__ uint2  g_Wp1[8 * 16 * 32];          // W1
__device__ uint2  g_Wp2[8 * 16 * 32];          // W2
__device__ uint2  g_Wcp[8 * 5 * 32];           // Wc (J=5)

// ===========================================================================
// mma / ldmatrix helpers (sm_75/sm_80 PTX — no arch-accelerated features)
// ===========================================================================
__device__ __forceinline__ uint32_t smem_addr(const void* p) {
    return (uint32_t)__cvta_generic_to_shared(p);
}

__device__ __forceinline__ void ldm_x4(uint32_t* r, uint32_t addr) {
    asm volatile("ldmatrix.sync.aligned.m8n8.x4.shared.b16 {%0,%1,%2,%3}, [%4];"
                 : "=r"(r[0]), "=r"(r[1]), "=r"(r[2]), "=r"(r[3]) : "r"(addr));
}

__device__ __forceinline__ void mma16816(float* c, const uint32_t* a,
                                         uint32_t b0, uint32_t b1) {
    asm volatile(
        "mma.sync.aligned.m16n8k16.row.col.f32.f16.f16.f32 "
        "{%0,%1,%2,%3}, {%4,%5,%6,%7}, {%8,%9}, {%0,%1,%2,%3};"
        : "+f"(c[0]), "+f"(c[1]), "+f"(c[2]), "+f"(c[3])
        : "r"(a[0]), "r"(a[1]), "r"(a[2]), "r"(a[3]), "r"(b0), "r"(b1));
}

// ===========================================================================
// Boot: zero deg + dtype detection (256-odd-word prefix)
// ===========================================================================
__global__ void k_boot(const int* __restrict__ p, int twoE, int n) {
    int i = blockIdx.x * blockDim.x + threadIdx.x;
    if (i < n) g_deg[i] = 0;
    if (blockIdx.x == 0) {
        if (threadIdx.x == 0) g_is64 = 1;
        __syncthreads();
        int idx = 2 * threadIdx.x + 1;
        if (idx < twoE && p[idx] != 0) g_is64 = 0;
    }
}

__device__ __forceinline__ int load_edge(const void* ei, size_t idx, int is64) {
    if (is64) return (int)((const long long*)ei)[idx];
    return ((const int*)ei)[idx];
}

// ===========================================================================
// Weight fusion: Wc = W3 @ Wl, bc = b3 @ Wl + bl
// ===========================================================================
__global__ void __launch_bounds__(256) k_fuseW(const float* __restrict__ W3,
                                               const float* __restrict__ Wl,
                                               const float* __restrict__ b3,
                                               const float* __restrict__ bl)
{
    __shared__ float Wls[128 * 40];
    int tid = threadIdx.x;
    for (int i = tid; i < 128 * 40; i += 256) Wls[i] = Wl[i];
    __syncthreads();

    for (int o = tid; o < 128 * 40; o += 256) {
        int i = o / 40, n = o % 40;
        float s = 0.f;
        #pragma unroll 8
        for (int k = 0; k < 128; k++)
            s = fmaf(W3[(size_t)i * FDIM + k], Wls[k * 40 + n], s);
        g_Wc[o] = s;
    }
    if (tid < 40) {
        float s = bl[tid];
        #pragma unroll 8
        for (int k = 0; k < 128; k++)
            s = fmaf(b3[k], Wls[k * 40 + tid], s);
        g_bc[tid] = s;
    }
}

// ===========================================================================
// Weight prepack into per-fragment order:
// out[(s*J + j)*32 + lane] = {b0,b1}; b0 = {W[16s+(l&3)*2][8j+(l>>2)], k+1}
// ===========================================================================
__global__ void k_packW(const float* __restrict__ W, int ncols, int J,
                        uint2* __restrict__ out)
{
    int t = blockIdx.x * blockDim.x + threadIdx.x;
    if (t >= 8 * J * 32) return;
    int lane = t & 31;
    int j = (t >> 5) % J;
    int s = t / (J * 32);
    int k0 = s * 16 + (lane & 3) * 2;
    int n  = j * 8 + (lane >> 2);
    __half2 b0 = __floats2half2_rn(W[(size_t)k0 * ncols + n],
                                   W[(size_t)(k0 + 1) * ncols + n]);
    __half2 b1 = __floats2half2_rn(W[(size_t)(k0 + 8) * ncols + n],
                                   W[(size_t)(k0 + 9) * ncols + n]);
    uint2 o;
    o.x = *(uint32_t*)&b0;
    o.y = *(uint32_t*)&b1;
    out[t] = o;
}

// ===========================================================================
// CSR build
// ===========================================================================
__global__ void k_count_deg(const void* __restrict__ ei, int E, int n) {
    int e = blockIdx.x * blockDim.x + threadIdx.x;
    if (e >= E) return;
    int is64 = g_is64;
    int d = load_edge(ei, (size_t)E + e, is64);
    if ((unsigned)d < (unsigned)n) atomicAdd(&g_deg[d], 1);
}

__global__ void k_dis(int n) {
    int i = blockIdx.x * blockDim.x + threadIdx.x;
    if (i < n) g_dis[i] = rsqrtf((float)(g_deg[i] + 1));
}

__global__ void __launch_bounds__(256) k_scan_block(int n) {
    __shared__ int s[256];
    int tid = threadIdx.x;
    int i = blockIdx.x * 256 + tid;
    int v = (i < n) ? g_deg[i] : 0;
    s[tid] = v;
    __syncthreads();
    for (int off = 1; off < 256; off <<= 1) {
        int t = (tid >= off) ? s[tid - off] : 0;
        __syncthreads();
        s[tid] += t;
        __syncthreads();
    }
    if (i < n) g_rowp[i] = s[tid] - v;
    if (tid == 255 && blockIdx.x < 512) g_bsum[blockIdx.x] = s[255];
}

__global__ void __launch_bounds__(512) k_scan_spine(int nb) {
    __shared__ int s[512];
    int tid = threadIdx.x;
    int v = (tid < nb) ? g_bsum[tid] : 0;
    s[tid] = v;
    __syncthreads();
    for (int off = 1; off < 512; off <<= 1) {
        int t = (tid >= off) ? s[tid - off] : 0;
        __syncthreads();
        s[tid] += t;
        __syncthreads();
    }
    g_boff[tid] = s[tid] - v;
}

__global__ void k_finalize(int n, int E) {
    int i = blockIdx.x * blockDim.x + threadIdx.x;
    if (i >= n) return;
    int r = g_rowp[i] + g_boff[(i >> 8) & 511];
    g_rowp[i] = r;
    g_cursor[i] = r;
    if (i == 0) g_rowp[n] = E;
}

__global__ void k_scatter(const void* __restrict__ ei, int E, int n) {
    int e = blockIdx.x * blockDim.x + threadIdx.x;
    if (e >= E) return;
    int is64 = g_is64;
    int s = load_edge(ei, (size_t)e, is64);
    int d = load_edge(ei, (size_t)E + e, is64);
    if ((unsigned)s >= (unsigned)n || (unsigned)d >= (unsigned)n) return;
    int pos = atomicAdd(&g_cursor[d], 1);
    if ((unsigned)pos < (unsigned)NEDGES) g_col[pos] = s;
}

// ===========================================================================
// Agg helpers (unchanged, bounds-guarded)
// ===========================================================================
__device__ __forceinline__ void acc_h8(float* a, uint4 v) {
    __half2* p = (__half2*)&v;
    float2 f0 = __half22float2(p[0]);
    float2 f1 = __half22float2(p[1]);
    float2 f2 = __half22float2(p[2]);
    float2 f3 = __half22float2(p[3]);
    a[0] += f0.x; a[1] += f0.y; a[2] += f1.x; a[3] += f1.y;
    a[4] += f2.x; a[5] += f2.y; a[6] += f3.x; a[7] += f3.y;
}

__device__ __forceinline__ void agg_node(const __half* __restrict__ H,
                                         int node, int hl, int n, int E,
                                         float* a)
{
    int beg = g_rowp[node];
    int end = g_rowp[node + 1];
    if (beg < 0) beg = 0;
    if (end > E) end = E;

    uint4 sv = __ldg((const uint4*)(H + (size_t)node * FDIM) + hl);
    {
        __half2* p = (__half2*)&sv;
        float2 f0 = __half22float2(p[0]);
        float2 f1 = __half22float2(p[1]);
        float2 f2 = __half22float2(p[2]);
        float2 f3 = __half22float2(p[3]);
        a[0] = f0.x; a[1] = f0.y; a[2] = f1.x; a[3] = f1.y;
        a[4] = f2.x; a[5] = f2.y; a[6] = f3.x; a[7] = f3.y;
    }

    int e = beg;
    for (; e + 2 <= end; e += 2) {
        int s0 = g_col[e];
        int s1 = g_col[e + 1];
        if ((unsigned)s0 >= (unsigned)n) s0 = 0;
        if ((unsigned)s1 >= (unsigned)n) s1 = 0;
        uint4 v0 = __ldg((const uint4*)(H + (size_t)s0 * FDIM) + hl);
        uint4 v1 = __ldg((const uint4*)(H + (size_t)s1 * FDIM) + hl);
        acc_h8(a, v0);
        acc_h8(a, v1);
    }
    if (e < end) {
        int s0 = g_col[e];
        if ((unsigned)s0 >= (unsigned)n) s0 = 0;
        uint4 v0 = __ldg((const uint4*)(H + (size_t)s0 * FDIM) + hl);
        acc_h8(a, v0);
    }
}

// ===========================================================================
// MMA phase (shared): Xs_h [32][SA] fp16 @ Wp (J=16) -> Hout fp16 [*,128]
// 4 warps: warp w covers n in [32w, 32w+32) = n-tiles 4w..4w+3.
// ===========================================================================
__device__ __forceinline__ void mma_phase128(const __half* Xs_h,
                                             const uint2* __restrict__ Wp,
                                             __half* __restrict__ Hout,
                                             int t0, int n)
{
    int tid = threadIdx.x;
    int lane = tid & 31;
    int w    = tid >> 5;

    float c[2][4][4];
    #pragma unroll
    for (int m = 0; m < 2; m++)
        #pragma unroll
        for (int j = 0; j < 4; j++)
            #pragma unroll
            for (int r = 0; r < 4; r++) c[m][j][r] = 0.f;

    // ldmatrix source address (row = lane&15, col block = (lane>>4)*8)
    uint32_t base = smem_addr(Xs_h);
    int arow = lane & 15;
    int acol = (lane >> 4) << 3;

    #pragma unroll
    for (int s = 0; s < 8; s++) {
        uint32_t a0[4], a1[4];
        ldm_x4(a0, base + (uint32_t)(((0 + arow) * SA + s * 16 + acol) * 2));
        ldm_x4(a1, base + (uint32_t)(((16 + arow) * SA + s * 16 + acol) * 2));

        #pragma unroll
        for (int jj = 0; jj < 4; jj++) {
            int j = w * 4 + jj;
            uint2 b = __ldg(&Wp[(s * 16 + j) * 32 + lane]);
            mma16816(c[0][jj], a0, b.x, b.y);
            mma16816(c[1][jj], a1, b.x, b.y);
        }
    }

    #pragma unroll
    for (int m = 0; m < 2; m++) {
        int row0 = t0 + m * 16 + (lane >> 2);
        int row1 = row0 + 8;
        float ds0 = (row0 < n) ? g_dis[row0] : 0.f;
        float ds1 = (row1 < n) ? g_dis[row1] : 0.f;
        #pragma unroll
        for (int jj = 0; jj < 4; jj++) {
            int col = w * 32 + jj * 8 + (lane & 3) * 2;
            if (row0 < n) {
                __half2 h = __floats2half2_rn(c[m][jj][0] * ds0, c[m][jj][1] * ds0);
                *(__half2*)&Hout[(size_t)row0 * FDIM + col] = h;
            }
            if (row1 < n) {
                __half2 h = __floats2half2_rn(c[m][jj][2] * ds1, c[m][jj][3] * ds1);
                *(__half2*)&Hout[(size_t)row1 * FDIM + col] = h;
            }
        }
    }
}

// ===========================================================================
// Layer 1: stage X (fp32) -> fp16 smem, then MMA with Wp1.
// ===========================================================================
__global__ void __launch_bounds__(128)
k_gemm1(const float* __restrict__ X, __half* __restrict__ H, int n)
{
    __shared__ __align__(16) __half Xs_h[32 * SA];
    int tid = threadIdx.x;
    int t0 = blockIdx.x * 32;

    #pragma unroll
    for (int i = 0; i < 8; i++) {
        int idx4 = (tid + i * 128) * 4;
        int row = idx4 >> 7;
        int col = idx4 & 127;
        int grow = t0 + row;
        float4 v = make_float4(0.f, 0.f, 0.f, 0.f);
        if (grow < n) v = *(const float4*)&X[(size_t)grow * FDIM + col];
        union { __half2 h[2]; uint2 u; } cv;
        cv.h[0] = __floats2half2_rn(v.x, v.y);
        cv.h[1] = __floats2half2_rn(v.z, v.w);
        *(uint2*)&Xs_h[row * SA + col] = cv.u;
    }
    __syncthreads();
    mma_phase128(Xs_h, g_Wp1, H, t0, n);
}

// ===========================================================================
// FUSED layer 2: agg(Hin) + bias + relu -> fp16 smem; MMA with Wp2 -> Hout.
// ===========================================================================
__global__ void __launch_bounds__(128)
k_fused2(const __half* __restrict__ Hin, __half* __restrict__ Hout,
         const float* __restrict__ bias, int n, int E)
{
    __shared__ __align__(16) __half Xs_h[32 * SA];
    int tid = threadIdx.x;
    int t0 = blockIdx.x * 32;

    {
        int hwid = tid >> 4;
        int hl   = tid & 15;
        float b[8];
        #pragma unroll
        for (int i = 0; i < 8; i++) b[i] = bias[hl * 8 + i];

        #pragma unroll
        for (int pass = 0; pass < 4; pass++) {
            int local = pass * 8 + hwid;
            int node = t0 + local;
            float a[8] = {0, 0, 0, 0, 0, 0, 0, 0};
            float di = 0.f;
            if (node < n) {
                di = g_dis[node];
                agg_node(Hin, node, hl, n, E, a);
            }
            union { __half2 h[4]; uint4 u; } cv;
            #pragma unroll
            for (int i = 0; i < 4; i++) {
                float v0 = fmaxf(fmaf(a[2 * i],     di, b[2 * i]),     0.f);
                float v1 = fmaxf(fmaf(a[2 * i + 1], di, b[2 * i + 1]), 0.f);
                cv.h[i] = __floats2half2_rn(v0, v1);
            }
            *(uint4*)&Xs_h[local * SA + hl * 8] = cv.u;
        }
    }
    __syncthreads();
    mma_phase128(Xs_h, g_Wp2, Hout, t0, n);
}

// ===========================================================================
// FUSED layer 3: agg(Hin) + b2 + relu -> fp16 smem; MMA (J=5) -> G fp16 [*,40]
// ===========================================================================
__global__ void __launch_bounds__(128)
k_fused3(const __half* __restrict__ Hin, __half* __restrict__ G,
         const float* __restrict__ bias, int n, int E)
{
    __shared__ __align__(16) __half Xs_h[32 * SA];
    int tid = threadIdx.x;
    int t0 = blockIdx.x * 32;

    {
        int hwid = tid >> 4;
        int hl   = tid & 15;
        float b[8];
        #pragma unroll
        for (int i = 0; i < 8; i++) b[i] = bias[hl * 8 + i];

        #pragma unroll
        for (int pass = 0; pass < 4; pass++) {
            int local = pass * 8 + hwid;
            int node = t0 + local;
            float a[8] = {0, 0, 0, 0, 0, 0, 0, 0};
            float di = 0.f;
            if (node < n) {
                di = g_dis[node];
                agg_node(Hin, node, hl, n, E, a);
            }
            union { __half2 h[4]; uint4 u; } cv;
            #pragma unroll
            for (int i = 0; i < 4; i++) {
                float v0 = fmaxf(fmaf(a[2 * i],     di, b[2 * i]),     0.f);
                float v1 = fmaxf(fmaf(a[2 * i + 1], di, b[2 * i + 1]), 0.f);
                cv.h[i] = __floats2half2_rn(v0, v1);
            }
            *(uint4*)&Xs_h[local * SA + hl * 8] = cv.u;
        }
    }
    __syncthreads();

    // MMA: J=5 n-tiles over 40 cols; warp w handles j = w, w+4(<5)
    int lane = tid & 31;
    int w    = tid >> 5;
    uint32_t base = smem_addr(Xs_h);
    int arow = lane & 15;
    int acol = (lane >> 4) << 3;

    float c[2][2][4];   // [m][jslot][reg], jslot 0: j=w, 1: j=w+4 (w==0 only)
    #pragma unroll
    for (int m = 0; m < 2; m++)
        #pragma unroll
        for (int js = 0; js < 2; js++)
            #pragma unroll
            for (int r = 0; r < 4; r++) c[m][js][r] = 0.f;

    int nj = (w == 0) ? 2 : 1;

    #pragma unroll
    for (int s = 0; s < 8; s++) {
        uint32_t a0[4], a1[4];
        ldm_x4(a0, base + (uint32_t)(((0 + arow) * SA + s * 16 + acol) * 2));
        ldm_x4(a1, base + (uint32_t)(((16 + arow) * SA + s * 16 + acol) * 2));

        for (int js = 0; js < nj; js++) {
            int j = w + js * 4;
            uint2 b = __ldg(&g_Wcp[(s * 5 + j) * 32 + lane]);
            mma16816(c[0][js], a0, b.x, b.y);
            mma16816(c[1][js], a1, b.x, b.y);
        }
    }

    #pragma unroll
    for (int m = 0; m < 2; m++) {
        int row0 = t0 + m * 16 + (lane >> 2);
        int row1 = row0 + 8;
        float ds0 = (row0 < n) ? g_dis[row0] : 0.f;
        float ds1 = (row1 < n) ? g_dis[row1] : 0.f;
        for (int js = 0; js < nj; js++) {
            int col = (w + js * 4) * 8 + (lane & 3) * 2;
            if (row0 < n) {
                __half2 h = __floats2half2_rn(c[m][js][0] * ds0, c[m][js][1] * ds0);
                *(__half2*)&G[(size_t)row0 * 40 + col] = h;
            }
            if (row1 < n) {
                __half2 h = __floats2half2_rn(c[m][js][2] * ds1, c[m][js][3] * ds1);
                *(__half2*)&G[(size_t)row1 * 40 + col] = h;
            }
        }
    }
}

// ===========================================================================
// Layer-3 aggregation (fp16, 40-wide): OUT = dis[d]*(G'[d] + sum G'[s]) + bc
// ===========================================================================
__global__ void __launch_bounds__(256)
k_agg40(const __half* __restrict__ G, float* __restrict__ OUT, int n, int E)
{
    int hw = (blockIdx.x * blockDim.x + threadIdx.x) >> 4;
    int l  = threadIdx.x & 15;
    if (hw >= n) return;
    bool act = l < 10;
    int  c   = l * 4;

    float di = g_dis[hw];
    int beg = g_rowp[hw];
    int end = g_rowp[hw + 1];
    if (beg < 0) beg = 0;
    if (end > E) end = E;

    float a0 = 0.f, a1 = 0.f, a2 = 0.f, a3 = 0.f;
    if (act) {
        uint2 sv = __ldg((const uint2*)(G + (size_t)hw * 40) + l);
        __half2* p = (__half2*)&sv;
        float2 f0 = __half22float2(p[0]);
        float2 f1 = __half22float2(p[1]);
        a0 = f0.x; a1 = f0.y; a2 = f1.x; a3 = f1.y;
    }

    int e = beg;
    for (; e + 2 <= end; e += 2) {
        int s0 = g_col[e];
        int s1 = g_col[e + 1];
        if ((unsigned)s0 >= (unsigned)n) s0 = 0;
        if ((unsigned)s1 >= (unsigned)n) s1 = 0;
        if (act) {
            uint2 v0 = __ldg((const uint2*)(G + (size_t)s0 * 40) + l);
            uint2 v1 = __ldg((const uint2*)(G + (size_t)s1 * 40) + l);
            __half2* p0 = (__half2*)&v0;
            __half2* p1 = (__half2*)&v1;
            float2 f;
            f = __half22float2(p0[0]); a0 += f.x; a1 += f.y;
            f = __half22float2(p0[1]); a2 += f.x; a3 += f.y;
            f = __half22float2(p1[0]); a0 += f.x; a1 += f.y;
            f = __half22float2(p1[1]); a2 += f.x; a3 += f.y;
        }
    }
    if (e < end) {
        int s0 = g_col[e];
        if ((unsigned)s0 >= (unsigned)n) s0 = 0;
        if (act) {
            uint2 v0 = __ldg((const uint2*)(G + (size_t)s0 * 40) + l);
            __half2* p0 = (__half2*)&v0;
            float2 f;
            f = __half22float2(p0[0]); a0 += f.x; a1 += f.y;
            f = __half22float2(p0[1]); a2 += f.x; a3 += f.y;
        }
    }

    if (act) {
        float4 o;
        o.x = fmaf(a0, di, g_bc[c]);
        o.y = fmaf(a1, di, g_bc[c + 1]);
        o.z = fmaf(a2, di, g_bc[c + 2]);
        o.w = fmaf(a3, di, g_bc[c + 3]);
        *(float4*)&OUT[(size_t)hw * 40 + c] = o;
    }
}

// ===========================================================================
extern "C" void kernel_launch(void* const* d_in, const int* in_sizes, int n_in,
                              void* d_out, int out_size)
{
    const float* x  = (const float*)d_in[0];
    const void*  ei = d_in[1];
    const float* W1 = (const float*)d_in[2];
    const float* b1 = (const float*)d_in[3];
    const float* W2 = (const float*)d_in[4];
    const float* b2 = (const float*)d_in[5];
    const float* W3 = (const float*)d_in[6];
    const float* b3 = (const float*)d_in[7];
    const float* Wl = (const float*)d_in[8];
    const float* bl = (const float*)d_in[9];
    float* out = (float*)d_out;

    int N = in_sizes[0] / FDIM;
    int E = in_sizes[1] / 2;
    if (N > NNODES) N = NNODES;
    if (E > NEDGES) E = NEDGES;

    __half *hp = nullptr, *h2p = nullptr, *gp = nullptr;
    float  *wcp_f = nullptr;
    uint2  *wp1 = nullptr, *wp2 = nullptr, *wcp = nullptr;
    cudaGetSymbolAddress((void**)&hp,  g_h);
    cudaGetSymbolAddress((void**)&h2p, g_h2);
    cudaGetSymbolAddress((void**)&gp,  g_g3);
    cudaGetSymbolAddress((void**)&wcp_f, g_Wc);
    cudaGetSymbolAddress((void**)&wp1, g_Wp1);
    cudaGetSymbolAddress((void**)&wp2, g_Wp2);
    cudaGetSymbolAddress((void**)&wcp, g_Wcp);

    static cudaStream_t s2 = nullptr;
    static cudaEvent_t evFork, evCsr;
    if (!s2) {
        cudaStreamCreateWithFlags(&s2, cudaStreamNonBlocking);
        cudaEventCreateWithFlags(&evFork, cudaEventDisableTiming);
        cudaEventCreateWithFlags(&evCsr,  cudaEventDisableTiming);
    }

    int nb = (N + 255) / 256;
    int eb = (E + 255) / 256;
    int tile_blocks = (N + 31) / 32;
    int agg40_blocks = (N * 16 + 255) / 256;

    // --- Serial prefix: deg + dis + W prepack (needed by gemm1) ---
    k_boot     <<<nb, 256>>>((const int*)ei, 2 * E, N);
    k_count_deg<<<eb, 256>>>(ei, E, N);
    k_dis      <<<nb, 256>>>(N);
    k_packW    <<<16, 256>>>(W1, 128, 16, wp1);

    // --- Fork: CSR tail + fuseW + remaining prepacks on s2 ---
    cudaEventRecord(evFork, 0);
    cudaStreamWaitEvent(s2, evFork, 0);
    k_scan_block<<<nb, 256, 0, s2>>>(N);
    k_scan_spine<<<1, 512, 0, s2>>>(nb);
    k_finalize  <<<nb, 256, 0, s2>>>(N, E);
    k_scatter   <<<eb, 256, 0, s2>>>(ei, E, N);
    k_fuseW     <<<1, 256, 0, s2>>>(W3, Wl, b3, bl);
    k_packW     <<<16, 256, 0, s2>>>(W2, 128, 16, wp2);
    k_packW     <<<5, 256, 0, s2>>>(wcp_f, 40, 5, wcp);
    cudaEventRecord(evCsr, s2);

    k_gemm1<<<tile_blocks, 128>>>(x, hp, N);
    cudaStreamWaitEvent(0, evCsr, 0);

    // --- Fused layer chain ---
    k_fused2<<<tile_blocks, 128>>>(hp, h2p, b1, N, E);
    k_fused3<<<tile_blocks, 128>>>(h2p, gp, b2, N, E);
    k_agg40 <<<agg40_blocks, 256>>>(gp, out, N, E);
}

// round 16
// speedup vs baseline: 2.2951x; 1.0528x over previous
#include <cuda_runtime.h>
#include <cuda_fp16.h>
#include <cstdint>

#define NNODES 100000
#define NEDGES 1600000
#define FDIM   128
#define SA     136            // padded smem A stride (halfs): 272 B, conflict-free

// Scratch (device globals — no allocation allowed anywhere)
__device__ __half g_h [(size_t)NNODES * FDIM]; // layer-1 messages (fp16)
__device__ __half g_h2[(size_t)NNODES * FDIM]; // layer-2 messages (fp16)
__device__ __half g_g3[(size_t)NNODES * 40];   // layer-3 fused messages (fp16)
__device__ float  g_dis[NNODES];               // (deg+1)^{-1/2}
__device__ int    g_deg[NNODES];
__device__ int    g_rowp[NNODES + 1];
__device__ int    g_cursor[NNODES];
__device__ int    g_col[NEDGES];
__device__ int    g_bsum[512];
__device__ int    g_boff[512];
__device__ int    g_is64;
__device__ float  g_Wc[128 * 40];              // W3 @ Wl (fp32)
__device__ float  g_bc[40];                    // b3 @ Wl + bl
// mma-fragment-ordered weights: [s(8)][j(J)][lane(32)] x uint2 {b0,b1}
__device__ uint2  g_Wp1[8 * 16 * 32];          // W1
__device__ uint2  g_Wp2[8 * 16 * 32];          // W2
__device__ uint2  g_Wcp[8 * 5 * 32];           // Wc (J=5)

// ===========================================================================
// mma / ldmatrix helpers (sm_75/sm_80 PTX — no arch-accelerated features)
// ===========================================================================
__device__ __forceinline__ uint32_t smem_addr(const void* p) {
    return (uint32_t)__cvta_generic_to_shared(p);
}

__device__ __forceinline__ void ldm_x4(uint32_t* r, uint32_t addr) {
    asm volatile("ldmatrix.sync.aligned.m8n8.x4.shared.b16 {%0,%1,%2,%3}, [%4];"
                 : "=r"(r[0]), "=r"(r[1]), "=r"(r[2]), "=r"(r[3]) : "r"(addr));
}

__device__ __forceinline__ void mma16816(float* c, const uint32_t* a,
                                         uint32_t b0, uint32_t b1) {
    asm volatile(
        "mma.sync.aligned.m16n8k16.row.col.f32.f16.f16.f32 "
        "{%0,%1,%2,%3}, {%4,%5,%6,%7}, {%8,%9}, {%0,%1,%2,%3};"
        : "+f"(c[0]), "+f"(c[1]), "+f"(c[2]), "+f"(c[3])
        : "r"(a[0]), "r"(a[1]), "r"(a[2]), "r"(a[3]), "r"(b0), "r"(b1));
}

// ===========================================================================
// Boot: zero deg + dtype detection (256-odd-word prefix)
// ===========================================================================
__global__ void k_boot(const int* __restrict__ p, int twoE, int n) {
    int i = blockIdx.x * blockDim.x + threadIdx.x;
    if (i < n) g_deg[i] = 0;
    if (blockIdx.x == 0) {
        if (threadIdx.x == 0) g_is64 = 1;
        __syncthreads();
        int idx = 2 * threadIdx.x + 1;
        if (idx < twoE && p[idx] != 0) g_is64 = 0;
    }
}

__device__ __forceinline__ int load_edge(const void* ei, size_t idx, int is64) {
    if (is64) return (int)((const long long*)ei)[idx];
    return ((const int*)ei)[idx];
}

// ===========================================================================
// Weight fusion: Wc = W3 @ Wl, bc = b3 @ Wl + bl
// ===========================================================================
__global__ void __launch_bounds__(256) k_fuseW(const float* __restrict__ W3,
                                               const float* __restrict__ Wl,
                                               const float* __restrict__ b3,
                                               const float* __restrict__ bl)
{
    __shared__ float Wls[128 * 40];
    int tid = threadIdx.x;
    for (int i = tid; i < 128 * 40; i += 256) Wls[i] = Wl[i];
    __syncthreads();

    for (int o = tid; o < 128 * 40; o += 256) {
        int i = o / 40, n = o % 40;
        float s = 0.f;
        #pragma unroll 8
        for (int k = 0; k < 128; k++)
            s = fmaf(W3[(size_t)i * FDIM + k], Wls[k * 40 + n], s);
        g_Wc[o] = s;
    }
    if (tid < 40) {
        float s = bl[tid];
        #pragma unroll 8
        for (int k = 0; k < 128; k++)
            s = fmaf(b3[k], Wls[k * 40 + tid], s);
        g_bc[tid] = s;
    }
}

// ===========================================================================
// Weight prepack into per-fragment order
// ===========================================================================
__global__ void k_packW(const float* __restrict__ W, int ncols, int J,
                        uint2* __restrict__ out)
{
    int t = blockIdx.x * blockDim.x + threadIdx.x;
    if (t >= 8 * J * 32) return;
    int lane = t & 31;
    int j = (t >> 5) % J;
    int s = t / (J * 32);
    int k0 = s * 16 + (lane & 3) * 2;
    int n  = j * 8 + (lane >> 2);
    __half2 b0 = __floats2half2_rn(W[(size_t)k0 * ncols + n],
                                   W[(size_t)(k0 + 1) * ncols + n]);
    __half2 b1 = __floats2half2_rn(W[(size_t)(k0 + 8) * ncols + n],
                                   W[(size_t)(k0 + 9) * ncols + n]);
    uint2 o;
    o.x = *(uint32_t*)&b0;
    o.y = *(uint32_t*)&b1;
    out[t] = o;
}

// ===========================================================================
// CSR build
// ===========================================================================
__global__ void k_count_deg(const void* __restrict__ ei, int E, int n) {
    int e = blockIdx.x * blockDim.x + threadIdx.x;
    if (e >= E) return;
    int is64 = g_is64;
    int d = load_edge(ei, (size_t)E + e, is64);
    if ((unsigned)d < (unsigned)n) atomicAdd(&g_deg[d], 1);
}

__global__ void k_dis(int n) {
    int i = blockIdx.x * blockDim.x + threadIdx.x;
    if (i < n) g_dis[i] = rsqrtf((float)(g_deg[i] + 1));
}

__global__ void __launch_bounds__(256) k_scan_block(int n) {
    __shared__ int s[256];
    int tid = threadIdx.x;
    int i = blockIdx.x * 256 + tid;
    int v = (i < n) ? g_deg[i] : 0;
    s[tid] = v;
    __syncthreads();
    for (int off = 1; off < 256; off <<= 1) {
        int t = (tid >= off) ? s[tid - off] : 0;
        __syncthreads();
        s[tid] += t;
        __syncthreads();
    }
    if (i < n) g_rowp[i] = s[tid] - v;
    if (tid == 255 && blockIdx.x < 512) g_bsum[blockIdx.x] = s[255];
}

__global__ void __launch_bounds__(512) k_scan_spine(int nb) {
    __shared__ int s[512];
    int tid = threadIdx.x;
    int v = (tid < nb) ? g_bsum[tid] : 0;
    s[tid] = v;
    __syncthreads();
    for (int off = 1; off < 512; off <<= 1) {
        int t = (tid >= off) ? s[tid - off] : 0;
        __syncthreads();
        s[tid] += t;
        __syncthreads();
    }
    g_boff[tid] = s[tid] - v;
}

__global__ void k_finalize(int n, int E) {
    int i = blockIdx.x * blockDim.x + threadIdx.x;
    if (i >= n) return;
    int r = g_rowp[i] + g_boff[(i >> 8) & 511];
    g_rowp[i] = r;
    g_cursor[i] = r;
    if (i == 0) g_rowp[n] = E;
}

__global__ void k_scatter(const void* __restrict__ ei, int E, int n) {
    int e = blockIdx.x * blockDim.x + threadIdx.x;
    if (e >= E) return;
    int is64 = g_is64;
    int s = load_edge(ei, (size_t)e, is64);
    int d = load_edge(ei, (size_t)E + e, is64);
    if ((unsigned)s >= (unsigned)n || (unsigned)d >= (unsigned)n) return;
    int pos = atomicAdd(&g_cursor[d], 1);
    if ((unsigned)pos < (unsigned)NEDGES) g_col[pos] = s;
}

// ===========================================================================
// Agg helpers (bounds-guarded, unroll 4 for MLP)
// ===========================================================================
__device__ __forceinline__ void acc_h8(float* a, uint4 v) {
    __half2* p = (__half2*)&v;
    float2 f0 = __half22float2(p[0]);
    float2 f1 = __half22float2(p[1]);
    float2 f2 = __half22float2(p[2]);
    float2 f3 = __half22float2(p[3]);
    a[0] += f0.x; a[1] += f0.y; a[2] += f1.x; a[3] += f1.y;
    a[4] += f2.x; a[5] += f2.y; a[6] += f3.x; a[7] += f3.y;
}

__device__ __forceinline__ void agg_node(const __half* __restrict__ H,
                                         int node, int hl, int n, int E,
                                         float* a)
{
    int beg = g_rowp[node];
    int end = g_rowp[node + 1];
    if (beg < 0) beg = 0;
    if (end > E) end = E;

    uint4 sv = __ldg((const uint4*)(H + (size_t)node * FDIM) + hl);
    {
        __half2* p = (__half2*)&sv;
        float2 f0 = __half22float2(p[0]);
        float2 f1 = __half22float2(p[1]);
        float2 f2 = __half22float2(p[2]);
        float2 f3 = __half22float2(p[3]);
        a[0] = f0.x; a[1] = f0.y; a[2] = f1.x; a[3] = f1.y;
        a[4] = f2.x; a[5] = f2.y; a[6] = f3.x; a[7] = f3.y;
    }

    int e = beg;
    for (; e + 4 <= end; e += 4) {
        int s0 = g_col[e];
        int s1 = g_col[e + 1];
        int s2 = g_col[e + 2];
        int s3 = g_col[e + 3];
        if ((unsigned)s0 >= (unsigned)n) s0 = 0;
        if ((unsigned)s1 >= (unsigned)n) s1 = 0;
        if ((unsigned)s2 >= (unsigned)n) s2 = 0;
        if ((unsigned)s3 >= (unsigned)n) s3 = 0;
        uint4 v0 = __ldg((const uint4*)(H + (size_t)s0 * FDIM) + hl);
        uint4 v1 = __ldg((const uint4*)(H + (size_t)s1 * FDIM) + hl);
        uint4 v2 = __ldg((const uint4*)(H + (size_t)s2 * FDIM) + hl);
        uint4 v3 = __ldg((const uint4*)(H + (size_t)s3 * FDIM) + hl);
        acc_h8(a, v0);
        acc_h8(a, v1);
        acc_h8(a, v2);
        acc_h8(a, v3);
    }
    for (; e < end; e++) {
        int s0 = g_col[e];
        if ((unsigned)s0 >= (unsigned)n) s0 = 0;
        uint4 v0 = __ldg((const uint4*)(H + (size_t)s0 * FDIM) + hl);
        acc_h8(a, v0);
    }
}

// ===========================================================================
// MMA phase (shared): Xs_h [32][SA] fp16 @ Wp (J=16) -> Hout fp16 [*,128]
// ===========================================================================
__device__ __forceinline__ void mma_phase128(const __half* Xs_h,
                                             const uint2* __restrict__ Wp,
                                             __half* __restrict__ Hout,
                                             int t0, int n)
{
    int tid = threadIdx.x;
    int lane = tid & 31;
    int w    = tid >> 5;

    float c[2][4][4];
    #pragma unroll
    for (int m = 0; m < 2; m++)
        #pragma unroll
        for (int j = 0; j < 4; j++)
            #pragma unroll
            for (int r = 0; r < 4; r++) c[m][j][r] = 0.f;

    uint32_t base = smem_addr(Xs_h);
    int arow = lane & 15;
    int acol = (lane >> 4) << 3;

    #pragma unroll
    for (int s = 0; s < 8; s++) {
        uint32_t a0[4], a1[4];
        ldm_x4(a0, base + (uint32_t)(((0 + arow) * SA + s * 16 + acol) * 2));
        ldm_x4(a1, base + (uint32_t)(((16 + arow) * SA + s * 16 + acol) * 2));

        #pragma unroll
        for (int jj = 0; jj < 4; jj++) {
            int j = w * 4 + jj;
            uint2 b = __ldg(&Wp[(s * 16 + j) * 32 + lane]);
            mma16816(c[0][jj], a0, b.x, b.y);
            mma16816(c[1][jj], a1, b.x, b.y);
        }
    }

    #pragma unroll
    for (int m = 0; m < 2; m++) {
        int row0 = t0 + m * 16 + (lane >> 2);
        int row1 = row0 + 8;
        float ds0 = (row0 < n) ? g_dis[row0] : 0.f;
        float ds1 = (row1 < n) ? g_dis[row1] : 0.f;
        #pragma unroll
        for (int jj = 0; jj < 4; jj++) {
            int col = w * 32 + jj * 8 + (lane & 3) * 2;
            if (row0 < n) {
                __half2 h = __floats2half2_rn(c[m][jj][0] * ds0, c[m][jj][1] * ds0);
                *(__half2*)&Hout[(size_t)row0 * FDIM + col] = h;
            }
            if (row1 < n) {
                __half2 h = __floats2half2_rn(c[m][jj][2] * ds1, c[m][jj][3] * ds1);
                *(__half2*)&Hout[(size_t)row1 * FDIM + col] = h;
            }
        }
    }
}

// ===========================================================================
// Layer 1: stage X (fp32) -> fp16 smem, then MMA with Wp1.
// ===========================================================================
__global__ void __launch_bounds__(128)
k_gemm1(const float* __restrict__ X, __half* __restrict__ H, int n)
{
    __shared__ __align__(16) __half Xs_h[32 * SA];
    int tid = threadIdx.x;
    int t0 = blockIdx.x * 32;

    #pragma unroll
    for (int i = 0; i < 8; i++) {
        int idx4 = (tid + i * 128) * 4;
        int row = idx4 >> 7;
        int col = idx4 & 127;
        int grow = t0 + row;
        float4 v = make_float4(0.f, 0.f, 0.f, 0.f);
        if (grow < n) v = *(const float4*)&X[(size_t)grow * FDIM + col];
        union { __half2 h[2]; uint2 u; } cv;
        cv.h[0] = __floats2half2_rn(v.x, v.y);
        cv.h[1] = __floats2half2_rn(v.z, v.w);
        *(uint2*)&Xs_h[row * SA + col] = cv.u;
    }
    __syncthreads();
    mma_phase128(Xs_h, g_Wp1, H, t0, n);
}

// ===========================================================================
// FUSED layer 2: agg(Hin) + bias + relu -> fp16 smem; MMA with Wp2 -> Hout.
// ===========================================================================
__global__ void __launch_bounds__(128, 8)
k_fused2(const __half* __restrict__ Hin, __half* __restrict__ Hout,
         const float* __restrict__ bias, int n, int E)
{
    __shared__ __align__(16) __half Xs_h[32 * SA];
    int tid = threadIdx.x;
    int t0 = blockIdx.x * 32;

    {
        int hwid = tid >> 4;
        int hl   = tid & 15;
        float b[8];
        #pragma unroll
        for (int i = 0; i < 8; i++) b[i] = bias[hl * 8 + i];

        #pragma unroll
        for (int pass = 0; pass < 4; pass++) {
            int local = pass * 8 + hwid;
            int node = t0 + local;
            float a[8] = {0, 0, 0, 0, 0, 0, 0, 0};
            float di = 0.f;
            if (node < n) {
                di = g_dis[node];
                agg_node(Hin, node, hl, n, E, a);
            }
            union { __half2 h[4]; uint4 u; } cv;
            #pragma unroll
            for (int i = 0; i < 4; i++) {
                float v0 = fmaxf(fmaf(a[2 * i],     di, b[2 * i]),     0.f);
                float v1 = fmaxf(fmaf(a[2 * i + 1], di, b[2 * i + 1]), 0.f);
                cv.h[i] = __floats2half2_rn(v0, v1);
            }
            *(uint4*)&Xs_h[local * SA + hl * 8] = cv.u;
        }
    }
    __syncthreads();
    mma_phase128(Xs_h, g_Wp2, Hout, t0, n);
}

// ===========================================================================
// FUSED layer 3: agg(Hin) + b2 + relu -> fp16 smem; MMA (J=5) -> G fp16 [*,40]
// ===========================================================================
__global__ void __launch_bounds__(128, 8)
k_fused3(const __half* __restrict__ Hin, __half* __restrict__ G,
         const float* __restrict__ bias, int n, int E)
{
    __shared__ __align__(16) __half Xs_h[32 * SA];
    int tid = threadIdx.x;
    int t0 = blockIdx.x * 32;

    {
        int hwid = tid >> 4;
        int hl   = tid & 15;
        float b[8];
        #pragma unroll
        for (int i = 0; i < 8; i++) b[i] = bias[hl * 8 + i];

        #pragma unroll
        for (int pass = 0; pass < 4; pass++) {
            int local = pass * 8 + hwid;
            int node = t0 + local;
            float a[8] = {0, 0, 0, 0, 0, 0, 0, 0};
            float di = 0.f;
            if (node < n) {
                di = g_dis[node];
                agg_node(Hin, node, hl, n, E, a);
            }
            union { __half2 h[4]; uint4 u; } cv;
            #pragma unroll
            for (int i = 0; i < 4; i++) {
                float v0 = fmaxf(fmaf(a[2 * i],     di, b[2 * i]),     0.f);
                float v1 = fmaxf(fmaf(a[2 * i + 1], di, b[2 * i + 1]), 0.f);
                cv.h[i] = __floats2half2_rn(v0, v1);
            }
            *(uint4*)&Xs_h[local * SA + hl * 8] = cv.u;
        }
    }
    __syncthreads();

    // MMA: J=5 n-tiles over 40 cols; warp w handles j = w (and j=4 for w=0)
    int lane = tid & 31;
    int w    = tid >> 5;
    uint32_t base = smem_addr(Xs_h);
    int arow = lane & 15;
    int acol = (lane >> 4) << 3;

    float c[2][2][4];
    #pragma unroll
    for (int m = 0; m < 2; m++)
        #pragma unroll
        for (int js = 0; js < 2; js++)
            #pragma unroll
            for (int r = 0; r < 4; r++) c[m][js][r] = 0.f;

    int nj = (w == 0) ? 2 : 1;

    #pragma unroll
    for (int s = 0; s < 8; s++) {
        uint32_t a0[4], a1[4];
        ldm_x4(a0, base + (uint32_t)(((0 + arow) * SA + s * 16 + acol) * 2));
        ldm_x4(a1, base + (uint32_t)(((16 + arow) * SA + s * 16 + acol) * 2));

        for (int js = 0; js < nj; js++) {
            int j = w + js * 4;
            uint2 b = __ldg(&g_Wcp[(s * 5 + j) * 32 + lane]);
            mma16816(c[0][js], a0, b.x, b.y);
            mma16816(c[1][js], a1, b.x, b.y);
        }
    }

    #pragma unroll
    for (int m = 0; m < 2; m++) {
        int row0 = t0 + m * 16 + (lane >> 2);
        int row1 = row0 + 8;
        float ds0 = (row0 < n) ? g_dis[row0] : 0.f;
        float ds1 = (row1 < n) ? g_dis[row1] : 0.f;
        for (int js = 0; js < nj; js++) {
            int col = (w + js * 4) * 8 + (lane & 3) * 2;
            if (row0 < n) {
                __half2 h = __floats2half2_rn(c[m][js][0] * ds0, c[m][js][1] * ds0);
                *(__half2*)&G[(size_t)row0 * 40 + col] = h;
            }
            if (row1 < n) {
                __half2 h = __floats2half2_rn(c[m][js][2] * ds1, c[m][js][3] * ds1);
                *(__half2*)&G[(size_t)row1 * 40 + col] = h;
            }
        }
    }
}

// ===========================================================================
// Layer-3 aggregation (fp16, 40-wide): OUT = dis[d]*(G'[d] + sum G'[s]) + bc
// ===========================================================================
__global__ void __launch_bounds__(256)
k_agg40(const __half* __restrict__ G, float* __restrict__ OUT, int n, int E)
{
    int hw = (blockIdx.x * blockDim.x + threadIdx.x) >> 4;
    int l  = threadIdx.x & 15;
    if (hw >= n) return;
    bool act = l < 10;
    int  c   = l * 4;

    float di = g_dis[hw];
    int beg = g_rowp[hw];
    int end = g_rowp[hw + 1];
    if (beg < 0) beg = 0;
    if (end > E) end = E;

    float a0 = 0.f, a1 = 0.f, a2 = 0.f, a3 = 0.f;
    if (act) {
        uint2 sv = __ldg((const uint2*)(G + (size_t)hw * 40) + l);
        __half2* p = (__half2*)&sv;
        float2 f0 = __half22float2(p[0]);
        float2 f1 = __half22float2(p[1]);
        a0 = f0.x; a1 = f0.y; a2 = f1.x; a3 = f1.y;
    }

    int e = beg;
    for (; e + 4 <= end; e += 4) {
        int s0 = g_col[e];
        int s1 = g_col[e + 1];
        int s2 = g_col[e + 2];
        int s3 = g_col[e + 3];
        if ((unsigned)s0 >= (unsigned)n) s0 = 0;
        if ((unsigned)s1 >= (unsigned)n) s1 = 0;
        if ((unsigned)s2 >= (unsigned)n) s2 = 0;
        if ((unsigned)s3 >= (unsigned)n) s3 = 0;
        if (act) {
            uint2 v0 = __ldg((const uint2*)(G + (size_t)s0 * 40) + l);
            uint2 v1 = __ldg((const uint2*)(G + (size_t)s1 * 40) + l);
            uint2 v2 = __ldg((const uint2*)(G + (size_t)s2 * 40) + l);
            uint2 v3 = __ldg((const uint2*)(G + (size_t)s3 * 40) + l);
            __half2* p0 = (__half2*)&v0;
            __half2* p1 = (__half2*)&v1;
            __half2* p2 = (__half2*)&v2;
            __half2* p3 = (__half2*)&v3;
            float2 f;
            f = __half22float2(p0[0]); a0 += f.x; a1 += f.y;
            f = __half22float2(p0[1]); a2 += f.x; a3 += f.y;
            f = __half22float2(p1[0]); a0 += f.x; a1 += f.y;
            f = __half22float2(p1[1]); a2 += f.x; a3 += f.y;
            f = __half22float2(p2[0]); a0 += f.x; a1 += f.y;
            f = __half22float2(p2[1]); a2 += f.x; a3 += f.y;
            f = __half22float2(p3[0]); a0 += f.x; a1 += f.y;
            f = __half22float2(p3[1]); a2 += f.x; a3 += f.y;
        }
    }
    for (; e < end; e++) {
        int s0 = g_col[e];
        if ((unsigned)s0 >= (unsigned)n) s0 = 0;
        if (act) {
            uint2 v0 = __ldg((const uint2*)(G + (size_t)s0 * 40) + l);
            __half2* p0 = (__half2*)&v0;
            float2 f;
            f = __half22float2(p0[0]); a0 += f.x; a1 += f.y;
            f = __half22float2(p0[1]); a2 += f.x; a3 += f.y;
        }
    }

    if (act) {
        float4 o;
        o.x = fmaf(a0, di, g_bc[c]);
        o.y = fmaf(a1, di, g_bc[c + 1]);
        o.z = fmaf(a2, di, g_bc[c + 2]);
        o.w = fmaf(a3, di, g_bc[c + 3]);
        *(float4*)&OUT[(size_t)hw * 40 + c] = o;
    }
}

// ===========================================================================
extern "C" void kernel_launch(void* const* d_in, const int* in_sizes, int n_in,
                              void* d_out, int out_size)
{
    const float* x  = (const float*)d_in[0];
    const void*  ei = d_in[1];
    const float* W1 = (const float*)d_in[2];
    const float* b1 = (const float*)d_in[3];
    const float* W2 = (const float*)d_in[4];
    const float* b2 = (const float*)d_in[5];
    const float* W3 = (const float*)d_in[6];
    const float* b3 = (const float*)d_in[7];
    const float* Wl = (const float*)d_in[8];
    const float* bl = (const float*)d_in[9];
    float* out = (float*)d_out;

    int N = in_sizes[0] / FDIM;
    int E = in_sizes[1] / 2;
    if (N > NNODES) N = NNODES;
    if (E > NEDGES) E = NEDGES;

    __half *hp = nullptr, *h2p = nullptr, *gp = nullptr;
    float  *wcp_f = nullptr;
    uint2  *wp1 = nullptr, *wp2 = nullptr, *wcp = nullptr;
    cudaGetSymbolAddress((void**)&hp,  g_h);
    cudaGetSymbolAddress((void**)&h2p, g_h2);
    cudaGetSymbolAddress((void**)&gp,  g_g3);
    cudaGetSymbolAddress((void**)&wcp_f, g_Wc);
    cudaGetSymbolAddress((void**)&wp1, g_Wp1);
    cudaGetSymbolAddress((void**)&wp2, g_Wp2);
    cudaGetSymbolAddress((void**)&wcp, g_Wcp);

    static cudaStream_t s2 = nullptr;
    static cudaEvent_t evFork, evG1;
    if (!s2) {
        cudaStreamCreateWithFlags(&s2, cudaStreamNonBlocking);
        cudaEventCreateWithFlags(&evFork, cudaEventDisableTiming);
        cudaEventCreateWithFlags(&evG1,   cudaEventDisableTiming);
    }

    int nb = (N + 255) / 256;
    int eb = (E + 255) / 256;
    int tile_blocks = (N + 31) / 32;
    int agg40_blocks = (N * 16 + 255) / 256;

    // --- Main stream: critical CSR chain ---
    k_boot     <<<nb, 256>>>((const int*)ei, 2 * E, N);
    k_count_deg<<<eb, 256>>>(ei, E, N);
    k_dis      <<<nb, 256>>>(N);

    // Fork after dis: all weight prep + gemm1 on s2 (hides under CSR tail)
    cudaEventRecord(evFork, 0);
    cudaStreamWaitEvent(s2, evFork, 0);
    k_packW<<<16, 256, 0, s2>>>(W1, 128, 16, wp1);
    k_gemm1<<<tile_blocks, 128, 0, s2>>>(x, hp, N);
    k_fuseW<<<1, 256, 0, s2>>>(W3, Wl, b3, bl);
    k_packW<<<16, 256, 0, s2>>>(W2, 128, 16, wp2);
    k_packW<<<5, 256, 0, s2>>>(wcp_f, 40, 5, wcp);
    cudaEventRecord(evG1, s2);

    // CSR tail on main (concurrent with s2)
    k_scan_block<<<nb, 256>>>(N);
    k_scan_spine<<<1, 512>>>(nb);
    k_finalize  <<<nb, 256>>>(N, E);
    k_scatter   <<<eb, 256>>>(ei, E, N);

    cudaStreamWaitEvent(0, evG1, 0);   // join: fused2 needs H1 + W2p

    // --- Fused layer chain ---
    k_fused2<<<tile_blocks, 128>>>(hp, h2p, b1, N, E);
    k_fused3<<<tile_blocks, 128>>>(h2p, gp, b2, N, E);
    k_agg40 <<<agg40_blocks, 256>>>(gp, out, N, E);
}

// round 17
// speedup vs baseline: 3.3284x; 1.4502x over previous
#include <cuda_runtime.h>
#include <cuda_fp16.h>
#include <cstdint>

#define NNODES 100000
#define NEDGES 1600000
#define FDIM   128
#define SA     136            // padded smem A stride (halfs): 272 B, conflict-free

// Scratch (device globals — no allocation allowed anywhere)
__device__ __half g_h [(size_t)NNODES * FDIM]; // layer-1 messages (fp16)
__device__ __half g_h2[(size_t)NNODES * FDIM]; // layer-2 messages (fp16)
__device__ __half g_g3[(size_t)NNODES * 40];   // layer-3 fused messages (fp16)
__device__ float  g_dis[NNODES];               // (deg+1)^{-1/2}
__device__ int    g_deg[NNODES];
__device__ int    g_rowp[NNODES + 1];
__device__ int    g_cursor[NNODES];
__device__ int    g_col[NEDGES];
__device__ int    g_bsum[512];
__device__ int    g_boff[512];
__device__ int    g_is64;
__device__ float  g_Wc[128 * 40];              // W3 @ Wl (fp32)
__device__ float  g_bc[40];                    // b3 @ Wl + bl
// mma-fragment-ordered weights: [s(8)][j(J)][lane(32)] x uint2 {b0,b1}
__device__ uint2  g_Wp1[8 * 16 * 32];          // W1
__device__ uint2  g_Wp2[8 * 16 * 32];          // W2
__device__ uint2  g_Wcp[8 * 5 * 32];           // Wc (J=5)

// ===========================================================================
// mma / ldmatrix helpers (sm_75/sm_80 PTX — no arch-accelerated features)
// ===========================================================================
__device__ __forceinline__ uint32_t smem_addr(const void* p) {
    return (uint32_t)__cvta_generic_to_shared(p);
}

__device__ __forceinline__ void ldm_x4(uint32_t* r, uint32_t addr) {
    asm volatile("ldmatrix.sync.aligned.m8n8.x4.shared.b16 {%0,%1,%2,%3}, [%4];"
                 : "=r"(r[0]), "=r"(r[1]), "=r"(r[2]), "=r"(r[3]) : "r"(addr));
}

__device__ __forceinline__ void mma16816(float* c, const uint32_t* a,
                                         uint32_t b0, uint32_t b1) {
    asm volatile(
        "mma.sync.aligned.m16n8k16.row.col.f32.f16.f16.f32 "
        "{%0,%1,%2,%3}, {%4,%5,%6,%7}, {%8,%9}, {%0,%1,%2,%3};"
        : "+f"(c[0]), "+f"(c[1]), "+f"(c[2]), "+f"(c[3])
        : "r"(a[0]), "r"(a[1]), "r"(a[2]), "r"(a[3]), "r"(b0), "r"(b1));
}

// ===========================================================================
// Boot: zero deg + dtype detection (256-odd-word prefix)
// ===========================================================================
__global__ void k_boot(const int* __restrict__ p, int twoE, int n) {
    int i = blockIdx.x * blockDim.x + threadIdx.x;
    if (i < n) g_deg[i] = 0;
    if (blockIdx.x == 0) {
        if (threadIdx.x == 0) g_is64 = 1;
        __syncthreads();
        int idx = 2 * threadIdx.x + 1;
        if (idx < twoE && p[idx] != 0) g_is64 = 0;
    }
}

__device__ __forceinline__ int load_edge(const void* ei, size_t idx, int is64) {
    if (is64) return (int)((const long long*)ei)[idx];
    return ((const int*)ei)[idx];
}

// ===========================================================================
// Weight fusion: Wc = W3 @ Wl, bc = b3 @ Wl + bl
// ===========================================================================
__global__ void __launch_bounds__(256) k_fuseW(const float* __restrict__ W3,
                                               const float* __restrict__ Wl,
                                               const float* __restrict__ b3,
                                               const float* __restrict__ bl)
{
    __shared__ float Wls[128 * 40];
    int tid = threadIdx.x;
    for (int i = tid; i < 128 * 40; i += 256) Wls[i] = Wl[i];
    __syncthreads();

    for (int o = tid; o < 128 * 40; o += 256) {
        int i = o / 40, n = o % 40;
        float s = 0.f;
        #pragma unroll 8
        for (int k = 0; k < 128; k++)
            s = fmaf(W3[(size_t)i * FDIM + k], Wls[k * 40 + n], s);
        g_Wc[o] = s;
    }
    if (tid < 40) {
        float s = bl[tid];
        #pragma unroll 8
        for (int k = 0; k < 128; k++)
            s = fmaf(b3[k], Wls[k * 40 + tid], s);
        g_bc[tid] = s;
    }
}

// ===========================================================================
// Weight prepack into per-fragment order
// ===========================================================================
__global__ void k_packW(const float* __restrict__ W, int ncols, int J,
                        uint2* __restrict__ out)
{
    int t = blockIdx.x * blockDim.x + threadIdx.x;
    if (t >= 8 * J * 32) return;
    int lane = t & 31;
    int j = (t >> 5) % J;
    int s = t / (J * 32);
    int k0 = s * 16 + (lane & 3) * 2;
    int n  = j * 8 + (lane >> 2);
    __half2 b0 = __floats2half2_rn(W[(size_t)k0 * ncols + n],
                                   W[(size_t)(k0 + 1) * ncols + n]);
    __half2 b1 = __floats2half2_rn(W[(size_t)(k0 + 8) * ncols + n],
                                   W[(size_t)(k0 + 9) * ncols + n]);
    uint2 o;
    o.x = *(uint32_t*)&b0;
    o.y = *(uint32_t*)&b1;
    out[t] = o;
}

// ===========================================================================
// CSR build (2 edges/thread, vectorized loads)
// ===========================================================================
__global__ void k_count_deg(const void* __restrict__ ei, int E, int n) {
    int t = blockIdx.x * blockDim.x + threadIdx.x;
    int e = 2 * t;
    if (e >= E) return;
    int is64 = g_is64;
    int d0, d1 = -1;
    if (is64) {
        if (e + 2 <= E) {
            longlong2 v = __ldg((const longlong2*)((const long long*)ei + E + e));
            d0 = (int)v.x; d1 = (int)v.y;
        } else {
            d0 = (int)((const long long*)ei)[(size_t)E + e];
        }
    } else {
        if (e + 2 <= E) {
            int2 v = __ldg((const int2*)((const int*)ei + E + e));
            d0 = v.x; d1 = v.y;
        } else {
            d0 = ((const int*)ei)[(size_t)E + e];
        }
    }
    if ((unsigned)d0 < (unsigned)n) atomicAdd(&g_deg[d0], 1);
    if ((unsigned)d1 < (unsigned)n) atomicAdd(&g_deg[d1], 1);
}

__global__ void k_dis(int n) {
    int i = blockIdx.x * blockDim.x + threadIdx.x;
    if (i < n) g_dis[i] = rsqrtf((float)(g_deg[i] + 1));
}

__global__ void __launch_bounds__(256) k_scan_block(int n) {
    __shared__ int s[256];
    int tid = threadIdx.x;
    int i = blockIdx.x * 256 + tid;
    int v = (i < n) ? g_deg[i] : 0;
    s[tid] = v;
    __syncthreads();
    for (int off = 1; off < 256; off <<= 1) {
        int t = (tid >= off) ? s[tid - off] : 0;
        __syncthreads();
        s[tid] += t;
        __syncthreads();
    }
    if (i < n) g_rowp[i] = s[tid] - v;
    if (tid == 255 && blockIdx.x < 512) g_bsum[blockIdx.x] = s[255];
}

__global__ void __launch_bounds__(512) k_scan_spine(int nb) {
    __shared__ int s[512];
    int tid = threadIdx.x;
    int v = (tid < nb) ? g_bsum[tid] : 0;
    s[tid] = v;
    __syncthreads();
    for (int off = 1; off < 512; off <<= 1) {
        int t = (tid >= off) ? s[tid - off] : 0;
        __syncthreads();
        s[tid] += t;
        __syncthreads();
    }
    g_boff[tid] = s[tid] - v;
}

__global__ void k_finalize(int n, int E) {
    int i = blockIdx.x * blockDim.x + threadIdx.x;
    if (i >= n) return;
    int r = g_rowp[i] + g_boff[(i >> 8) & 511];
    g_rowp[i] = r;
    g_cursor[i] = r;
    if (i == 0) g_rowp[n] = E;
}

__global__ void k_scatter(const void* __restrict__ ei, int E, int n) {
    int t = blockIdx.x * blockDim.x + threadIdx.x;
    int e = 2 * t;
    if (e >= E) return;
    int is64 = g_is64;
    int s0, d0, s1 = -1, d1 = -1;
    if (is64) {
        const long long* p = (const long long*)ei;
        if (e + 2 <= E) {
            longlong2 sv = __ldg((const longlong2*)(p + e));
            longlong2 dv = __ldg((const longlong2*)(p + E + e));
            s0 = (int)sv.x; s1 = (int)sv.y;
            d0 = (int)dv.x; d1 = (int)dv.y;
        } else {
            s0 = (int)p[e]; d0 = (int)p[(size_t)E + e];
        }
    } else {
        const int* p = (const int*)ei;
        if (e + 2 <= E) {
            int2 sv = __ldg((const int2*)(p + e));
            int2 dv = __ldg((const int2*)(p + E + e));
            s0 = sv.x; s1 = sv.y;
            d0 = dv.x; d1 = dv.y;
        } else {
            s0 = p[e]; d0 = p[(size_t)E + e];
        }
    }
    if ((unsigned)s0 < (unsigned)n && (unsigned)d0 < (unsigned)n) {
        int pos = atomicAdd(&g_cursor[d0], 1);
        if ((unsigned)pos < (unsigned)NEDGES) g_col[pos] = s0;
    }
    if ((unsigned)s1 < (unsigned)n && (unsigned)d1 < (unsigned)n) {
        int pos = atomicAdd(&g_cursor[d1], 1);
        if ((unsigned)pos < (unsigned)NEDGES) g_col[pos] = s1;
    }
}

// ===========================================================================
// Agg helpers (bounds-guarded, unroll 4 for MLP)
// ===========================================================================
__device__ __forceinline__ void acc_h8(float* a, uint4 v) {
    __half2* p = (__half2*)&v;
    float2 f0 = __half22float2(p[0]);
    float2 f1 = __half22float2(p[1]);
    float2 f2 = __half22float2(p[2]);
    float2 f3 = __half22float2(p[3]);
    a[0] += f0.x; a[1] += f0.y; a[2] += f1.x; a[3] += f1.y;
    a[4] += f2.x; a[5] += f2.y; a[6] += f3.x; a[7] += f3.y;
}

__device__ __forceinline__ void agg_node(const __half* __restrict__ H,
                                         int node, int hl, int n, int E,
                                         float* a)
{
    int beg = g_rowp[node];
    int end = g_rowp[node + 1];
    if (beg < 0) beg = 0;
    if (end > E) end = E;

    uint4 sv = __ldg((const uint4*)(H + (size_t)node * FDIM) + hl);
    {
        __half2* p = (__half2*)&sv;
        float2 f0 = __half22float2(p[0]);
        float2 f1 = __half22float2(p[1]);
        float2 f2 = __half22float2(p[2]);
        float2 f3 = __half22float2(p[3]);
        a[0] = f0.x; a[1] = f0.y; a[2] = f1.x; a[3] = f1.y;
        a[4] = f2.x; a[5] = f2.y; a[6] = f3.x; a[7] = f3.y;
    }

    int e = beg;
    for (; e + 4 <= end; e += 4) {
        int s0 = g_col[e];
        int s1 = g_col[e + 1];
        int s2 = g_col[e + 2];
        int s3 = g_col[e + 3];
        if ((unsigned)s0 >= (unsigned)n) s0 = 0;
        if ((unsigned)s1 >= (unsigned)n) s1 = 0;
        if ((unsigned)s2 >= (unsigned)n) s2 = 0;
        if ((unsigned)s3 >= (unsigned)n) s3 = 0;
        uint4 v0 = __ldg((const uint4*)(H + (size_t)s0 * FDIM) + hl);
        uint4 v1 = __ldg((const uint4*)(H + (size_t)s1 * FDIM) + hl);
        uint4 v2 = __ldg((const uint4*)(H + (size_t)s2 * FDIM) + hl);
        uint4 v3 = __ldg((const uint4*)(H + (size_t)s3 * FDIM) + hl);
        acc_h8(a, v0);
        acc_h8(a, v1);
        acc_h8(a, v2);
        acc_h8(a, v3);
    }
    for (; e < end; e++) {
        int s0 = g_col[e];
        if ((unsigned)s0 >= (unsigned)n) s0 = 0;
        uint4 v0 = __ldg((const uint4*)(H + (size_t)s0 * FDIM) + hl);
        acc_h8(a, v0);
    }
}

// ===========================================================================
// MMA phase (shared): Xs_h [32][SA] fp16 @ Wp (J=16) -> Hout fp16 [*,128]
// ===========================================================================
__device__ __forceinline__ void mma_phase128(const __half* Xs_h,
                                             const uint2* __restrict__ Wp,
                                             __half* __restrict__ Hout,
                                             int t0, int n)
{
    int tid = threadIdx.x;
    int lane = tid & 31;
    int w    = tid >> 5;

    float c[2][4][4];
    #pragma unroll
    for (int m = 0; m < 2; m++)
        #pragma unroll
        for (int j = 0; j < 4; j++)
            #pragma unroll
            for (int r = 0; r < 4; r++) c[m][j][r] = 0.f;

    uint32_t base = smem_addr(Xs_h);
    int arow = lane & 15;
    int acol = (lane >> 4) << 3;

    #pragma unroll
    for (int s = 0; s < 8; s++) {
        uint32_t a0[4], a1[4];
        ldm_x4(a0, base + (uint32_t)(((0 + arow) * SA + s * 16 + acol) * 2));
        ldm_x4(a1, base + (uint32_t)(((16 + arow) * SA + s * 16 + acol) * 2));

        #pragma unroll
        for (int jj = 0; jj < 4; jj++) {
            int j = w * 4 + jj;
            uint2 b = __ldg(&Wp[(s * 16 + j) * 32 + lane]);
            mma16816(c[0][jj], a0, b.x, b.y);
            mma16816(c[1][jj], a1, b.x, b.y);
        }
    }

    #pragma unroll
    for (int m = 0; m < 2; m++) {
        int row0 = t0 + m * 16 + (lane >> 2);
        int row1 = row0 + 8;
        float ds0 = (row0 < n) ? g_dis[row0] : 0.f;
        float ds1 = (row1 < n) ? g_dis[row1] : 0.f;
        #pragma unroll
        for (int jj = 0; jj < 4; jj++) {
            int col = w * 32 + jj * 8 + (lane & 3) * 2;
            if (row0 < n) {
                __half2 h = __floats2half2_rn(c[m][jj][0] * ds0, c[m][jj][1] * ds0);
                *(__half2*)&Hout[(size_t)row0 * FDIM + col] = h;
            }
            if (row1 < n) {
                __half2 h = __floats2half2_rn(c[m][jj][2] * ds1, c[m][jj][3] * ds1);
                *(__half2*)&Hout[(size_t)row1 * FDIM + col] = h;
            }
        }
    }
}

// ===========================================================================
// Layer 1: stage X (fp32) -> fp16 smem, then MMA with Wp1.
// ===========================================================================
__global__ void __launch_bounds__(128)
k_gemm1(const float* __restrict__ X, __half* __restrict__ H, int n)
{
    __shared__ __align__(16) __half Xs_h[32 * SA];
    int tid = threadIdx.x;
    int t0 = blockIdx.x * 32;

    #pragma unroll
    for (int i = 0; i < 8; i++) {
        int idx4 = (tid + i * 128) * 4;
        int row = idx4 >> 7;
        int col = idx4 & 127;
        int grow = t0 + row;
        float4 v = make_float4(0.f, 0.f, 0.f, 0.f);
        if (grow < n) v = *(const float4*)&X[(size_t)grow * FDIM + col];
        union { __half2 h[2]; uint2 u; } cv;
        cv.h[0] = __floats2half2_rn(v.x, v.y);
        cv.h[1] = __floats2half2_rn(v.z, v.w);
        *(uint2*)&Xs_h[row * SA + col] = cv.u;
    }
    __syncthreads();
    mma_phase128(Xs_h, g_Wp1, H, t0, n);
}

// ===========================================================================
// FUSED layer 2: agg(Hin) + bias + relu -> fp16 smem; MMA with Wp2 -> Hout.
// ===========================================================================
__global__ void __launch_bounds__(128, 8)
k_fused2(const __half* __restrict__ Hin, __half* __restrict__ Hout,
         const float* __restrict__ bias, int n, int E)
{
    __shared__ __align__(16) __half Xs_h[32 * SA];
    int tid = threadIdx.x;
    int t0 = blockIdx.x * 32;

    {
        int hwid = tid >> 4;
        int hl   = tid & 15;
        float b[8];
        #pragma unroll
        for (int i = 0; i < 8; i++) b[i] = bias[hl * 8 + i];

        #pragma unroll
        for (int pass = 0; pass < 4; pass++) {
            int local = pass * 8 + hwid;
            int node = t0 + local;
            float a[8] = {0, 0, 0, 0, 0, 0, 0, 0};
            float di = 0.f;
            if (node < n) {
                di = g_dis[node];
                agg_node(Hin, node, hl, n, E, a);
            }
            union { __half2 h[4]; uint4 u; } cv;
            #pragma unroll
            for (int i = 0; i < 4; i++) {
                float v0 = fmaxf(fmaf(a[2 * i],     di, b[2 * i]),     0.f);
                float v1 = fmaxf(fmaf(a[2 * i + 1], di, b[2 * i + 1]), 0.f);
                cv.h[i] = __floats2half2_rn(v0, v1);
            }
            *(uint4*)&Xs_h[local * SA + hl * 8] = cv.u;
        }
    }
    __syncthreads();
    mma_phase128(Xs_h, g_Wp2, Hout, t0, n);
}

// ===========================================================================
// FUSED layer 3: agg(Hin) + b2 + relu -> fp16 smem; MMA (J=5) -> G fp16 [*,40]
// ===========================================================================
__global__ void __launch_bounds__(128, 8)
k_fused3(const __half* __restrict__ Hin, __half* __restrict__ G,
         const float* __restrict__ bias, int n, int E)
{
    __shared__ __align__(16) __half Xs_h[32 * SA];
    int tid = threadIdx.x;
    int t0 = blockIdx.x * 32;

    {
        int hwid = tid >> 4;
        int hl   = tid & 15;
        float b[8];
        #pragma unroll
        for (int i = 0; i < 8; i++) b[i] = bias[hl * 8 + i];

        #pragma unroll
        for (int pass = 0; pass < 4; pass++) {
            int local = pass * 8 + hwid;
            int node = t0 + local;
            float a[8] = {0, 0, 0, 0, 0, 0, 0, 0};
            float di = 0.f;
            if (node < n) {
                di = g_dis[node];
                agg_node(Hin, node, hl, n, E, a);
            }
            union { __half2 h[4]; uint4 u; } cv;
            #pragma unroll
            for (int i = 0; i < 4; i++) {
                float v0 = fmaxf(fmaf(a[2 * i],     di, b[2 * i]),     0.f);
                float v1 = fmaxf(fmaf(a[2 * i + 1], di, b[2 * i + 1]), 0.f);
                cv.h[i] = __floats2half2_rn(v0, v1);
            }
            *(uint4*)&Xs_h[local * SA + hl * 8] = cv.u;
        }
    }
    __syncthreads();

    // MMA: J=5 n-tiles over 40 cols; warp w handles j = w (and j=4 for w=0)
    int lane = tid & 31;
    int w    = tid >> 5;
    uint32_t base = smem_addr(Xs_h);
    int arow = lane & 15;
    int acol = (lane >> 4) << 3;

    float c[2][2][4];
    #pragma unroll
    for (int m = 0; m < 2; m++)
        #pragma unroll
        for (int js = 0; js < 2; js++)
            #pragma unroll
            for (int r = 0; r < 4; r++) c[m][js][r] = 0.f;

    int nj = (w == 0) ? 2 : 1;

    #pragma unroll
    for (int s = 0; s < 8; s++) {
        uint32_t a0[4], a1[4];
        ldm_x4(a0, base + (uint32_t)(((0 + arow) * SA + s * 16 + acol) * 2));
        ldm_x4(a1, base + (uint32_t)(((16 + arow) * SA + s * 16 + acol) * 2));

        for (int js = 0; js < nj; js++) {
            int j = w + js * 4;
            uint2 b = __ldg(&g_Wcp[(s * 5 + j) * 32 + lane]);
            mma16816(c[0][js], a0, b.x, b.y);
            mma16816(c[1][js], a1, b.x, b.y);
        }
    }

    #pragma unroll
    for (int m = 0; m < 2; m++) {
        int row0 = t0 + m * 16 + (lane >> 2);
        int row1 = row0 + 8;
        float ds0 = (row0 < n) ? g_dis[row0] : 0.f;
        float ds1 = (row1 < n) ? g_dis[row1] : 0.f;
        for (int js = 0; js < nj; js++) {
            int col = (w + js * 4) * 8 + (lane & 3) * 2;
            if (row0 < n) {
                __half2 h = __floats2half2_rn(c[m][js][0] * ds0, c[m][js][1] * ds0);
                *(__half2*)&G[(size_t)row0 * 40 + col] = h;
            }
            if (row1 < n) {
                __half2 h = __floats2half2_rn(c[m][js][2] * ds1, c[m][js][3] * ds1);
                *(__half2*)&G[(size_t)row1 * 40 + col] = h;
            }
        }
    }
}

// ===========================================================================
// Layer-3 aggregation (fp16, 40-wide): OUT = dis[d]*(G'[d] + sum G'[s]) + bc
// ===========================================================================
__global__ void __launch_bounds__(256)
k_agg40(const __half* __restrict__ G, float* __restrict__ OUT, int n, int E)
{
    int hw = (blockIdx.x * blockDim.x + threadIdx.x) >> 4;
    int l  = threadIdx.x & 15;
    if (hw >= n) return;
    bool act = l < 10;
    int  c   = l * 4;

    float di = g_dis[hw];
    int beg = g_rowp[hw];
    int end = g_rowp[hw + 1];
    if (beg < 0) beg = 0;
    if (end > E) end = E;

    float a0 = 0.f, a1 = 0.f, a2 = 0.f, a3 = 0.f;
    if (act) {
        uint2 sv = __ldg((const uint2*)(G + (size_t)hw * 40) + l);
        __half2* p = (__half2*)&sv;
        float2 f0 = __half22float2(p[0]);
        float2 f1 = __half22float2(p[1]);
        a0 = f0.x; a1 = f0.y; a2 = f1.x; a3 = f1.y;
    }

    int e = beg;
    for (; e + 4 <= end; e += 4) {
        int s0 = g_col[e];
        int s1 = g_col[e + 1];
        int s2 = g_col[e + 2];
        int s3 = g_col[e + 3];
        if ((unsigned)s0 >= (unsigned)n) s0 = 0;
        if ((unsigned)s1 >= (unsigned)n) s1 = 0;
        if ((unsigned)s2 >= (unsigned)n) s2 = 0;
        if ((unsigned)s3 >= (unsigned)n) s3 = 0;
        if (act) {
            uint2 v0 = __ldg((const uint2*)(G + (size_t)s0 * 40) + l);
            uint2 v1 = __ldg((const uint2*)(G + (size_t)s1 * 40) + l);
            uint2 v2 = __ldg((const uint2*)(G + (size_t)s2 * 40) + l);
            uint2 v3 = __ldg((const uint2*)(G + (size_t)s3 * 40) + l);
            __half2* p0 = (__half2*)&v0;
            __half2* p1 = (__half2*)&v1;
            __half2* p2 = (__half2*)&v2;
            __half2* p3 = (__half2*)&v3;
            float2 f;
            f = __half22float2(p0[0]); a0 += f.x; a1 += f.y;
            f = __half22float2(p0[1]); a2 += f.x; a3 += f.y;
            f = __half22float2(p1[0]); a0 += f.x; a1 += f.y;
            f = __half22float2(p1[1]); a2 += f.x; a3 += f.y;
            f = __half22float2(p2[0]); a0 += f.x; a1 += f.y;
            f = __half22float2(p2[1]); a2 += f.x; a3 += f.y;
            f = __half22float2(p3[0]); a0 += f.x; a1 += f.y;
            f = __half22float2(p3[1]); a2 += f.x; a3 += f.y;
        }
    }
    for (; e < end; e++) {
        int s0 = g_col[e];
        if ((unsigned)s0 >= (unsigned)n) s0 = 0;
        if (act) {
            uint2 v0 = __ldg((const uint2*)(G + (size_t)s0 * 40) + l);
            __half2* p0 = (__half2*)&v0;
            float2 f;
            f = __half22float2(p0[0]); a0 += f.x; a1 += f.y;
            f = __half22float2(p0[1]); a2 += f.x; a3 += f.y;
        }
    }

    if (act) {
        float4 o;
        o.x = fmaf(a0, di, g_bc[c]);
        o.y = fmaf(a1, di, g_bc[c + 1]);
        o.z = fmaf(a2, di, g_bc[c + 2]);
        o.w = fmaf(a3, di, g_bc[c + 3]);
        *(float4*)&OUT[(size_t)hw * 40 + c] = o;
    }
}

// ===========================================================================
extern "C" void kernel_launch(void* const* d_in, const int* in_sizes, int n_in,
                              void* d_out, int out_size)
{
    const float* x  = (const float*)d_in[0];
    const void*  ei = d_in[1];
    const float* W1 = (const float*)d_in[2];
    const float* b1 = (const float*)d_in[3];
    const float* W2 = (const float*)d_in[4];
    const float* b2 = (const float*)d_in[5];
    const float* W3 = (const float*)d_in[6];
    const float* b3 = (const float*)d_in[7];
    const float* Wl = (const float*)d_in[8];
    const float* bl = (const float*)d_in[9];
    float* out = (float*)d_out;

    int N = in_sizes[0] / FDIM;
    int E = in_sizes[1] / 2;
    if (N > NNODES) N = NNODES;
    if (E > NEDGES) E = NEDGES;

    __half *hp = nullptr, *h2p = nullptr, *gp = nullptr;
    float  *wcp_f = nullptr;
    uint2  *wp1 = nullptr, *wp2 = nullptr, *wcp = nullptr;
    cudaGetSymbolAddress((void**)&hp,  g_h);
    cudaGetSymbolAddress((void**)&h2p, g_h2);
    cudaGetSymbolAddress((void**)&gp,  g_g3);
    cudaGetSymbolAddress((void**)&wcp_f, g_Wc);
    cudaGetSymbolAddress((void**)&wp1, g_Wp1);
    cudaGetSymbolAddress((void**)&wp2, g_Wp2);
    cudaGetSymbolAddress((void**)&wcp, g_Wcp);

    static cudaStream_t s2 = nullptr;
    static cudaEvent_t evDis, evG1;
    if (!s2) {
        cudaStreamCreateWithFlags(&s2, cudaStreamNonBlocking);
        cudaEventCreateWithFlags(&evDis, cudaEventDisableTiming);
        cudaEventCreateWithFlags(&evG1,  cudaEventDisableTiming);
    }

    int nb = (N + 255) / 256;
    int eb2 = (E / 2 + 256) / 256;   // 2 edges per thread
    int tile_blocks = (N + 31) / 32;
    int agg40_blocks = (N * 16 + 255) / 256;

    // --- s2: weight prep starts immediately (depends only on weights) ---
    k_packW<<<16, 256, 0, s2>>>(W1, 128, 16, wp1);
    k_fuseW<<<1, 256, 0, s2>>>(W3, Wl, b3, bl);
    k_packW<<<16, 256, 0, s2>>>(W2, 128, 16, wp2);
    k_packW<<<5, 256, 0, s2>>>(wcp_f, 40, 5, wcp);

    // --- main: degree prefix ---
    k_boot     <<<nb, 256>>>((const int*)ei, 2 * E, N);
    k_count_deg<<<eb2, 256>>>(ei, E, N);
    k_dis      <<<nb, 256>>>(N);
    cudaEventRecord(evDis, 0);

    // --- s2: gemm1 after dis (needs Wp1 + dis) ---
    cudaStreamWaitEvent(s2, evDis, 0);
    k_gemm1<<<tile_blocks, 128, 0, s2>>>(x, hp, N);
    cudaEventRecord(evG1, s2);

    // --- main: CSR tail (concurrent with gemm1) ---
    k_scan_block<<<nb, 256>>>(N);
    k_scan_spine<<<1, 512>>>(nb);
    k_finalize  <<<nb, 256>>>(N, E);
    k_scatter   <<<eb2, 256>>>(ei, E, N);

    cudaStreamWaitEvent(0, evG1, 0);   // join: fused2 needs H1 + Wp2

    // --- Fused layer chain ---
    k_fused2<<<tile_blocks, 128>>>(hp, h2p, b1, N, E);
    k_fused3<<<tile_blocks, 128>>>(h2p, gp, b2, N, E);
    k_agg40 <<<agg40_blocks, 256>>>(gp, out, N, E);
}